// round 4
// baseline (speedup 1.0000x reference)
#include <cuda_runtime.h>
#include <cuda_bf16.h>
#include <math.h>
#include <stdint.h>

// Problem constants
#define NN    30000
#define NE    480000
#define HD    256
#define MPAD  30080      // 235*128
#define KTOT  768        // x_aug | h | t1
#define NCOL  1024       // 4 gates * 256, interleaved col' = j*4 + g
#define NH    (NN * HD)

// ---------------- static device scratch ----------------
__device__ float g_xaug[NN * HD];
__device__ float g_t1[NN * HD];
__device__ float g_deg[NN];
__device__ __align__(16) __nv_bfloat16 g_Ah[MPAD * KTOT];
__device__ __align__(16) __nv_bfloat16 g_Al[MPAD * KTOT];
__device__ __align__(16) __nv_bfloat16 g_Wh[NCOL * KTOT];   // W transposed [n'][k], n'=j*4+g
__device__ __align__(16) __nv_bfloat16 g_Wl[NCOL * KTOT];
__device__ __align__(16) __nv_bfloat16 g_Rh[MPAD * HD];     // relu(h0) split; pad rows stay 0
__device__ __align__(16) __nv_bfloat16 g_Rl[MPAD * HD];
__device__ __align__(16) __nv_bfloat16 g_WlTh[HD * HD];
__device__ __align__(16) __nv_bfloat16 g_WlTl[HD * HD];
// combined bias/peephole vectors
__device__ float g_bI[HD], g_bF[HD], g_bG[HD], g_bO[HD];
__device__ float g_wI[HD], g_wF[HD], g_wO[HD];

__device__ __forceinline__ float sigf(float x) { return 1.0f / (1.0f + __expf(-x)); }

__device__ __forceinline__ uint32_t smem_u32(const void* p) {
    uint32_t a;
    asm("{ .reg .u64 t; cvta.to.shared.u64 t, %1; cvt.u32.u64 %0, t; }" : "=r"(a) : "l"(p));
    return a;
}

// ---------------- init: copy x, zero t1/deg ----------------
__global__ __launch_bounds__(256) void k_init(const float* __restrict__ x) {
    int i = blockIdx.x * blockDim.x + threadIdx.x;
    if (i < NN * 64) {
        float4 v = reinterpret_cast<const float4*>(x)[i];
        reinterpret_cast<float4*>(g_xaug)[i] = v;
        reinterpret_cast<float4*>(g_t1)[i] = make_float4(0.f, 0.f, 0.f, 0.f);
        if (i < NN) g_deg[i] = 0.f;
    }
}

__global__ __launch_bounds__(256) void k_deg(const int* __restrict__ src,
                                             const float* __restrict__ ew) {
    int e = blockIdx.x * blockDim.x + threadIdx.x;
    if (e < NE) atomicAdd(&g_deg[src[e]], ew[e]);
}

__global__ __launch_bounds__(256) void k_dinv() {
    int i = blockIdx.x * blockDim.x + threadIdx.x;
    if (i < NN) {
        float d = g_deg[i];
        g_deg[i] = (d > 0.f) ? rsqrtf(fmaxf(d, 1e-12f)) : 0.f;
    }
}

// ---------------- fused edge pass: aug scatter + cheb t1 scatter ----------------
// 32 threads per edge, each handles 2 float4 (32B).
__global__ __launch_bounds__(256) void k_edge(
    const float* __restrict__ x, const float* __restrict__ h,
    const int* __restrict__ src, const int* __restrict__ dst,
    const int* __restrict__ snid, const int* __restrict__ dnid,
    const float* __restrict__ ew)
{
    int i = blockIdx.x * blockDim.x + threadIdx.x;
    if (i >= NE * 32) return;
    int e = i >> 5;
    int q = (i & 31) * 2;
    int s = src[e], d = dst[e], sn = snid[e], dn = dnid[e];
    float coef = -g_deg[s] * ew[e] * g_deg[d];

    const float4* x4 = reinterpret_cast<const float4*>(x);
    const float4* h4 = reinterpret_cast<const float4*>(h);
    float4* a4 = reinterpret_cast<float4*>(g_xaug);
    float4* t4 = reinterpret_cast<float4*>(g_t1);

    float4 s0 = x4[(size_t)sn * 64 + q];
    float4 s1 = x4[(size_t)sn * 64 + q + 1];
    atomicAdd(&a4[(size_t)s * 64 + q], s0);
    atomicAdd(&a4[(size_t)s * 64 + q + 1], s1);

    float4 d0 = x4[(size_t)dn * 64 + q];
    float4 d1 = x4[(size_t)dn * 64 + q + 1];
    atomicAdd(&a4[(size_t)d * 64 + q], d0);
    atomicAdd(&a4[(size_t)d * 64 + q + 1], d1);

    float4 h0 = h4[(size_t)s * 64 + q];
    float4 h1 = h4[(size_t)s * 64 + q + 1];
    atomicAdd(&t4[(size_t)d * 64 + q],
              make_float4(coef * h0.x, coef * h0.y, coef * h0.z, coef * h0.w));
    atomicAdd(&t4[(size_t)d * 64 + q + 1],
              make_float4(coef * h1.x, coef * h1.y, coef * h1.z, coef * h1.w));
}

// ---------------- fp32 -> bf16 hi/lo split helpers ----------------
__device__ __forceinline__ void split8(const float* v, uint4& hi4, uint4& lo4) {
    __nv_bfloat16 h[8], l[8];
#pragma unroll
    for (int t = 0; t < 8; t++) {
        h[t] = __float2bfloat16(v[t]);
        l[t] = __float2bfloat16(v[t] - __bfloat162float(h[t]));
    }
    hi4 = *reinterpret_cast<uint4*>(h);
    lo4 = *reinterpret_cast<uint4*>(l);
}

// A = [x_aug | h | t1] -> bf16 hi/lo; pad rows zero.
__global__ __launch_bounds__(256) void k_conv_A(const float* __restrict__ h) {
    int i = blockIdx.x * blockDim.x + threadIdx.x;   // over MPAD*96 chunks of 8
    if (i >= MPAD * 96) return;
    int row = i / 96;
    int c8 = i % 96;
    uint4 hi4, li4;
    if (row < NN) {
        const float4* srcp;
        int cc = c8 & 31;
        if (c8 < 32)       srcp = reinterpret_cast<const float4*>(g_xaug) + (size_t)row * 64 + cc * 2;
        else if (c8 < 64)  srcp = reinterpret_cast<const float4*>(h) + (size_t)row * 64 + cc * 2;
        else               srcp = reinterpret_cast<const float4*>(g_t1) + (size_t)row * 64 + cc * 2;
        float v[8];
        float4 a = srcp[0], b = srcp[1];
        v[0]=a.x; v[1]=a.y; v[2]=a.z; v[3]=a.w; v[4]=b.x; v[5]=b.y; v[6]=b.z; v[7]=b.w;
        split8(v, hi4, li4);
    } else {
        hi4 = make_uint4(0,0,0,0); li4 = hi4;
    }
    reinterpret_cast<uint4*>(g_Ah)[i] = hi4;
    reinterpret_cast<uint4*>(g_Al)[i] = li4;
}

// W pack with interleaved columns: n' = j*4 + g
__global__ __launch_bounds__(256) void k_conv_W(
    const float* __restrict__ Wi, const float* __restrict__ Wf,
    const float* __restrict__ Wg, const float* __restrict__ Wo,
    const float* __restrict__ Wci, const float* __restrict__ Wcf,
    const float* __restrict__ Wcg, const float* __restrict__ Wco)
{
    int i = blockIdx.x * blockDim.x + threadIdx.x;   // over NCOL*96
    if (i >= NCOL * 96) return;
    int n = i / 96;
    int kc = i % 96;
    int j = n >> 2, g = n & 3;
    const float* Win[4] = {Wi, Wf, Wg, Wo};
    const float* Wc[4]  = {Wci, Wcf, Wcg, Wco};
    float v[8];
#pragma unroll
    for (int t = 0; t < 8; t++) {
        int k = kc * 8 + t;
        if (k < 256)      v[t] = Win[g][k * 256 + j];
        else if (k < 512) v[t] = Wc[g][(k - 256) * 256 + j];
        else              v[t] = Wc[g][65536 + (k - 512) * 256 + j];
    }
    uint4 hi4, lo4;
    split8(v, hi4, lo4);
    reinterpret_cast<uint4*>(g_Wh)[i] = hi4;
    reinterpret_cast<uint4*>(g_Wl)[i] = lo4;
}

__global__ __launch_bounds__(256) void k_conv_Wlin(const float* __restrict__ Wlin) {
    int i = blockIdx.x * blockDim.x + threadIdx.x;   // over 256*32
    if (i >= HD * 32) return;
    int n = i / 32;
    int kc = i % 32;
    float v[8];
#pragma unroll
    for (int t = 0; t < 8; t++) v[t] = Wlin[(kc * 8 + t) * 256 + n];
    uint4 hi4, lo4;
    split8(v, hi4, lo4);
    reinterpret_cast<uint4*>(g_WlTh)[i] = hi4;
    reinterpret_cast<uint4*>(g_WlTl)[i] = lo4;
}

// combine bias vectors
__global__ void k_bias(const float* bci, const float* bcf, const float* bcg, const float* bco,
                       const float* bi, const float* bf, const float* bg, const float* bo,
                       const float* wci, const float* wcf, const float* wco) {
    int j = threadIdx.x;
    g_bI[j] = bci[j] + bi[j];
    g_bF[j] = bcf[j] + bf[j];
    g_bG[j] = bcg[j] + bg[j];
    g_bO[j] = bco[j] + bo[j];
    g_wI[j] = wci[j];
    g_wF[j] = wcf[j];
    g_wO[j] = wco[j];
}

// ============ bf16-split GEMM via mma.sync ============
#define BKG   32
#define NSTG  3
#define TSTR  80
#define TILEB (128 * TSTR)
#define STAGEB (4 * TILEB)
#define SMEM_GEMM (NSTG * STAGEB)

__device__ __forceinline__ void cp16(uint32_t saddr, const void* gaddr) {
    asm volatile("cp.async.cg.shared.global [%0], [%1], 16;" :: "r"(saddr), "l"(gaddr));
}
__device__ __forceinline__ void ldm_x4(uint32_t* r, uint32_t a) {
    asm volatile("ldmatrix.sync.aligned.m8n8.x4.shared.b16 {%0,%1,%2,%3}, [%4];"
                 : "=r"(r[0]), "=r"(r[1]), "=r"(r[2]), "=r"(r[3]) : "r"(a));
}
__device__ __forceinline__ void ldm_x2(uint32_t* r, uint32_t a) {
    asm volatile("ldmatrix.sync.aligned.m8n8.x2.shared.b16 {%0,%1}, [%2];"
                 : "=r"(r[0]), "=r"(r[1]) : "r"(a));
}
__device__ __forceinline__ void mma16816(float* c, const uint32_t* a, const uint32_t* b) {
    asm volatile(
        "mma.sync.aligned.m16n8k16.row.col.f32.bf16.bf16.f32 "
        "{%0,%1,%2,%3}, {%4,%5,%6,%7}, {%8,%9}, {%0,%1,%2,%3};"
        : "+f"(c[0]), "+f"(c[1]), "+f"(c[2]), "+f"(c[3])
        : "r"(a[0]), "r"(a[1]), "r"(a[2]), "r"(a[3]), "r"(b[0]), "r"(b[1]));
}

// MODE 0: plain epilogue (bias + fp32 store to C, rows < m_limit)
// MODE 1: fused gates epilogue (C unused for Z; writes h0/c_new to out, relu split to g_Rh/g_Rl)
template <int MODE>
__global__ __launch_bounds__(256) void k_mma(
    const __nv_bfloat16* __restrict__ Ah, const __nv_bfloat16* __restrict__ Al,
    const __nv_bfloat16* __restrict__ Bh, const __nv_bfloat16* __restrict__ Bl,
    float* __restrict__ C, int K, int Ncols, const float* __restrict__ bias, int m_limit,
    const float* __restrict__ cvec, float* __restrict__ out)
{
    extern __shared__ char smem[];
    const int tid = threadIdx.x;
    const int wid = tid >> 5;
    const int lane = tid & 31;
    const int m0 = blockIdx.y * 128;
    const int n0 = blockIdx.x * 128;
    const int nkt = K / BKG;
    const uint32_t sb = smem_u32(smem);

    const int wr = (wid >> 2) * 64;
    const int wc = (wid & 3) * 32;

    const int r0c = tid >> 2, c0c = tid & 3;
    const int r1c = (tid + 256) >> 2, c1c = tid & 3;

    float acc[4][4][4] = {};

    auto issue_stage = [&](int kt, int buf) {
        uint32_t s = sb + buf * STAGEB;
        const char* ahB = reinterpret_cast<const char*>(Ah);
        const char* alB = reinterpret_cast<const char*>(Al);
        const char* bhB = reinterpret_cast<const char*>(Bh);
        const char* blB = reinterpret_cast<const char*>(Bl);
        size_t kb = (size_t)kt * BKG * 2;
        {
            size_t ga = ((size_t)(m0 + r0c) * K) * 2 + kb + c0c * 16;
            size_t gb = ((size_t)(n0 + r0c) * K) * 2 + kb + c0c * 16;
            uint32_t so = r0c * TSTR + c0c * 16;
            cp16(s + so, ahB + ga);
            cp16(s + TILEB + so, alB + ga);
            cp16(s + 2 * TILEB + so, bhB + gb);
            cp16(s + 3 * TILEB + so, blB + gb);
        }
        {
            size_t ga = ((size_t)(m0 + r1c) * K) * 2 + kb + c1c * 16;
            size_t gb = ((size_t)(n0 + r1c) * K) * 2 + kb + c1c * 16;
            uint32_t so = r1c * TSTR + c1c * 16;
            cp16(s + so, ahB + ga);
            cp16(s + TILEB + so, alB + ga);
            cp16(s + 2 * TILEB + so, bhB + gb);
            cp16(s + 3 * TILEB + so, blB + gb);
        }
    };

    for (int s = 0; s < NSTG - 1; s++) {
        if (s < nkt) issue_stage(s, s);
        asm volatile("cp.async.commit_group;");
    }

    for (int kt = 0; kt < nkt; kt++) {
        asm volatile("cp.async.wait_group %0;" :: "n"(NSTG - 2));
        __syncthreads();

        uint32_t s = sb + (kt % NSTG) * STAGEB;
        uint32_t sAh = s, sAl = s + TILEB, sBh = s + 2 * TILEB, sBl = s + 3 * TILEB;

#pragma unroll
        for (int ks = 0; ks < 2; ks++) {
            uint32_t ah[4][4], al[4][4], bh[4][2], bl[4][2];
            uint32_t aoff = (wr + (lane & 15)) * TSTR + ks * 32 + ((lane >> 4) & 1) * 16;
#pragma unroll
            for (int mt = 0; mt < 4; mt++) {
                ldm_x4(ah[mt], sAh + aoff + mt * 16 * TSTR);
                ldm_x4(al[mt], sAl + aoff + mt * 16 * TSTR);
            }
            int l = lane & 15;
            uint32_t boff = (wc + (l & 7)) * TSTR + ks * 32 + ((l >> 3) & 1) * 16;
#pragma unroll
            for (int nt = 0; nt < 4; nt++) {
                ldm_x2(bh[nt], sBh + boff + nt * 8 * TSTR);
                ldm_x2(bl[nt], sBl + boff + nt * 8 * TSTR);
            }
#pragma unroll
            for (int mt = 0; mt < 4; mt++)
#pragma unroll
                for (int nt = 0; nt < 4; nt++) {
                    mma16816(acc[mt][nt], ah[mt], bh[nt]);
                    mma16816(acc[mt][nt], ah[mt], bl[nt]);
                    mma16816(acc[mt][nt], al[mt], bh[nt]);
                }
        }
        __syncthreads();
        int nk = kt + NSTG - 1;
        if (nk < nkt) issue_stage(nk, nk % NSTG);
        asm volatile("cp.async.commit_group;");
    }

    if (MODE == 0) {
#pragma unroll
        for (int mt = 0; mt < 4; mt++) {
            int rA = m0 + wr + mt * 16 + (lane >> 2);
            int rB = rA + 8;
#pragma unroll
            for (int nt = 0; nt < 4; nt++) {
                int col = n0 + wc + nt * 8 + (lane & 3) * 2;
                float bx = 0.f, by = 0.f;
                if (bias) { bx = bias[col]; by = bias[col + 1]; }
                if (rA < m_limit) {
                    float2 v = make_float2(acc[mt][nt][0] + bx, acc[mt][nt][1] + by);
                    *reinterpret_cast<float2*>(C + (size_t)rA * Ncols + col) = v;
                }
                if (rB < m_limit) {
                    float2 v = make_float2(acc[mt][nt][2] + bx, acc[mt][nt][3] + by);
                    *reinterpret_cast<float2*>(C + (size_t)rB * Ncols + col) = v;
                }
            }
        }
    } else {
        // fused gates: col' = j*4 + g. Lane pair (lane, lane^1) covers cols 4j..4j+3.
#pragma unroll
        for (int mt = 0; mt < 4; mt++) {
            int rbase = m0 + wr + mt * 16 + (lane >> 2);
#pragma unroll
            for (int nt = 0; nt < 4; nt++) {
                int jcol = n0 + wc + nt * 8 + (lane & 3) * 2;
                int j = jcol >> 2;
                int p = (jcol >> 1) & 1;   // 0: holds (i,f); 1: holds (g,o)
                float bI = g_bI[j], bF = g_bF[j], bG = g_bG[j], bO = g_bO[j];
                float wI = g_wI[j], wF = g_wF[j], wO = g_wO[j];
#pragma unroll
                for (int hh = 0; hh < 2; hh++) {
                    int row = rbase + hh * 8;
                    float z0 = acc[mt][nt][2 * hh];
                    float z1 = acc[mt][nt][2 * hh + 1];
                    float o0 = __shfl_xor_sync(0xffffffff, z0, 1);
                    float o1 = __shfl_xor_sync(0xffffffff, z1, 1);
                    float zi = p ? o0 : z0, zf = p ? o1 : z1;
                    float zg = p ? z0 : o0, zo = p ? z1 : o1;
                    if (row < NN) {
                        size_t off = (size_t)row * HD + j;
                        float cv = cvec[off];
                        float ig = sigf(zi + bI + wI * cv);
                        float fg = sigf(zf + bF + wF * cv);
                        float gg = tanhf(zg + bG);
                        float cn = fg * cv + ig * gg;
                        float og = sigf(zo + bO + wO * cn);
                        float h0 = og * tanhf(cn);
                        if (p == 0) {
                            out[NH + off] = h0;
                            out[2 * NH + off] = cn;
                        } else {
                            float r = fmaxf(h0, 0.f);
                            __nv_bfloat16 rh = __float2bfloat16(r);
                            __nv_bfloat16 rl = __float2bfloat16(r - __bfloat162float(rh));
                            g_Rh[off] = rh;
                            g_Rl[off] = rl;
                        }
                    }
                }
            }
        }
    }
}

// ---------------- launch ----------------
extern "C" void kernel_launch(void* const* d_in, const int* in_sizes, int n_in,
                              void* d_out, int out_size) {
    const float* x    = (const float*)d_in[0];
    const int*   ei   = (const int*)d_in[1];
    const float* ew   = (const float*)d_in[2];
    const float* h    = (const float*)d_in[3];
    const float* c    = (const float*)d_in[4];
    const int*   snid = (const int*)d_in[5];
    const int*   dnid = (const int*)d_in[6];
    const float* Wi   = (const float*)d_in[7];
    const float* Wf   = (const float*)d_in[8];
    const float* Wg   = (const float*)d_in[9];
    const float* Wo   = (const float*)d_in[10];
    const float* Wci  = (const float*)d_in[11];
    const float* Wcf  = (const float*)d_in[12];
    const float* Wcg  = (const float*)d_in[13];
    const float* Wco  = (const float*)d_in[14];
    const float* bci  = (const float*)d_in[15];
    const float* bcf  = (const float*)d_in[16];
    const float* bcg  = (const float*)d_in[17];
    const float* bco  = (const float*)d_in[18];

    const float *bi, *bf, *bg, *bo, *blin, *wci, *wcf, *wco, *Wlin;
    if (in_sizes[27] == 65536) {
        bi = (const float*)d_in[19]; bf = (const float*)d_in[20];
        bg = (const float*)d_in[21]; bo = (const float*)d_in[22];
        blin = (const float*)d_in[23];
        wci = (const float*)d_in[24]; wcf = (const float*)d_in[25];
        wco = (const float*)d_in[26];
        Wlin = (const float*)d_in[27];
    } else {
        wci = (const float*)d_in[19]; wcf = (const float*)d_in[20];
        wco = (const float*)d_in[21];
        bi = (const float*)d_in[22]; bf = (const float*)d_in[23];
        bg = (const float*)d_in[24]; bo = (const float*)d_in[25];
        Wlin = (const float*)d_in[26];
        blin = (const float*)d_in[27];
    }

    const int* src = ei;
    const int* dst = ei + NE;
    float* out = (float*)d_out;

    cudaFuncSetAttribute(k_mma<0>, cudaFuncAttributeMaxDynamicSharedMemorySize, SMEM_GEMM);
    cudaFuncSetAttribute(k_mma<1>, cudaFuncAttributeMaxDynamicSharedMemorySize, SMEM_GEMM);

    k_init<<<(NN * 64 + 255) / 256, 256>>>(x);
    k_conv_W<<<(NCOL * 96 + 255) / 256, 256>>>(Wi, Wf, Wg, Wo, Wci, Wcf, Wcg, Wco);
    k_conv_Wlin<<<(HD * 32 + 255) / 256, 256>>>(Wlin);
    k_bias<<<1, HD>>>(bci, bcf, bcg, bco, bi, bf, bg, bo, wci, wcf, wco);
    k_deg<<<(NE + 255) / 256, 256>>>(src, ew);
    k_dinv<<<(NN + 255) / 256, 256>>>();
    k_edge<<<(NE * 32) / 256, 256>>>(x, h, src, dst, snid, dnid, ew);
    k_conv_A<<<(MPAD * 96 + 255) / 256, 256>>>(h);

    float *Ah, *Al, *Wh, *Wl, *Rh, *Rl, *WlTh, *WlTl;
    cudaGetSymbolAddress((void**)&Ah, g_Ah);
    cudaGetSymbolAddress((void**)&Al, g_Al);
    cudaGetSymbolAddress((void**)&Wh, g_Wh);
    cudaGetSymbolAddress((void**)&Wl, g_Wl);
    cudaGetSymbolAddress((void**)&Rh, g_Rh);
    cudaGetSymbolAddress((void**)&Rl, g_Rl);
    cudaGetSymbolAddress((void**)&WlTh, g_WlTh);
    cudaGetSymbolAddress((void**)&WlTl, g_WlTl);

    // big GEMM with fused gates epilogue: writes h0/c_new to out, relu split to g_Rh/g_Rl
    {
        dim3 grid(NCOL / 128, MPAD / 128);
        k_mma<1><<<grid, 256, SMEM_GEMM>>>(
            (const __nv_bfloat16*)Ah, (const __nv_bfloat16*)Al,
            (const __nv_bfloat16*)Wh, (const __nv_bfloat16*)Wl,
            nullptr, KTOT, NCOL, nullptr, NN, c, out);
    }

    // small GEMM: h_out[NN x 256] = relu(h0) @ W_lin + b_lin
    {
        dim3 grid(HD / 128, MPAD / 128);
        k_mma<0><<<grid, 256, SMEM_GEMM>>>(
            (const __nv_bfloat16*)Rh, (const __nv_bfloat16*)Rl,
            (const __nv_bfloat16*)WlTh, (const __nv_bfloat16*)WlTl,
            out, HD, HD, blin, NN, nullptr, nullptr);
    }
}

// round 6
// speedup vs baseline: 1.1558x; 1.1558x over previous
#include <cuda_runtime.h>
#include <cuda_bf16.h>
#include <math.h>
#include <stdint.h>

// Problem constants
#define NN    30000
#define NE    480000
#define HD    256
#define MPAD  30080      // 235*128
#define KTOT  768        // x_aug | h | t1
#define NCOL  1024       // 4 gates * 256 (gate-blocked: col = g*256 + j)
#define NH    (NN * HD)

// ---------------- static device scratch ----------------
__device__ float g_xaug[NN * HD];
__device__ float g_t1[NN * HD];
__device__ float g_deg[NN];
__device__ float g_Z[MPAD * NCOL];                    // gate pre-activations (fp32)
__device__ __align__(16) __nv_bfloat16 g_Ah[MPAD * KTOT];
__device__ __align__(16) __nv_bfloat16 g_Al[MPAD * KTOT];
__device__ __align__(16) __nv_bfloat16 g_Wh[NCOL * KTOT];   // W transposed: [n][k]
__device__ __align__(16) __nv_bfloat16 g_Wl[NCOL * KTOT];
__device__ __align__(16) __nv_bfloat16 g_Rh[MPAD * HD];     // relu(h0) split
__device__ __align__(16) __nv_bfloat16 g_Rl[MPAD * HD];
__device__ __align__(16) __nv_bfloat16 g_WlTh[HD * HD];     // W_lin transposed split
__device__ __align__(16) __nv_bfloat16 g_WlTl[HD * HD];

__device__ __forceinline__ float sigf(float x) { return 1.0f / (1.0f + expf(-x)); }

__device__ __forceinline__ uint32_t smem_u32(const void* p) {
    uint32_t a;
    asm("{ .reg .u64 t; cvta.to.shared.u64 t, %1; cvt.u32.u64 %0, t; }" : "=r"(a) : "l"(p));
    return a;
}

// ---------------- init ----------------
__global__ __launch_bounds__(256) void k_init(const float* __restrict__ x) {
    int i = blockIdx.x * blockDim.x + threadIdx.x;
    if (i < NN * 64) {
        float4 v = reinterpret_cast<const float4*>(x)[i];
        reinterpret_cast<float4*>(g_xaug)[i] = v;
        reinterpret_cast<float4*>(g_t1)[i] = make_float4(0.f, 0.f, 0.f, 0.f);
        if (i < NN) g_deg[i] = 0.f;
    }
}

__global__ __launch_bounds__(256) void k_deg(const int* __restrict__ src,
                                             const float* __restrict__ ew) {
    int e = blockIdx.x * blockDim.x + threadIdx.x;
    if (e < NE) atomicAdd(&g_deg[src[e]], ew[e]);
}

__global__ __launch_bounds__(256) void k_dinv() {
    int i = blockIdx.x * blockDim.x + threadIdx.x;
    if (i < NN) {
        float d = g_deg[i];
        g_deg[i] = (d > 0.f) ? rsqrtf(fmaxf(d, 1e-12f)) : 0.f;
    }
}

// ---------------- fused edge pass: aug scatters + cheb t1 scatter ----------------
// One warp per edge; each lane handles 2 float4 (32B) of the 256B row.
__global__ __launch_bounds__(256) void k_edge(
    const float* __restrict__ x, const float* __restrict__ h,
    const int* __restrict__ src, const int* __restrict__ dst,
    const int* __restrict__ snid, const int* __restrict__ dnid,
    const float* __restrict__ ew)
{
    int i = blockIdx.x * blockDim.x + threadIdx.x;
    if (i >= NE * 32) return;
    int e = i >> 5;
    int q = (i & 31) * 2;
    int s = src[e], d = dst[e], sn = snid[e], dn = dnid[e];
    float coef = -g_deg[s] * ew[e] * g_deg[d];

    const float4* x4 = reinterpret_cast<const float4*>(x);
    const float4* h4 = reinterpret_cast<const float4*>(h);
    float4* a4 = reinterpret_cast<float4*>(g_xaug);
    float4* t4 = reinterpret_cast<float4*>(g_t1);

    float4 s0 = x4[(size_t)sn * 64 + q];
    float4 s1 = x4[(size_t)sn * 64 + q + 1];
    float4 d0 = x4[(size_t)dn * 64 + q];
    float4 d1 = x4[(size_t)dn * 64 + q + 1];
    float4 h0 = h4[(size_t)s * 64 + q];
    float4 h1 = h4[(size_t)s * 64 + q + 1];

    atomicAdd(&a4[(size_t)s * 64 + q], s0);
    atomicAdd(&a4[(size_t)s * 64 + q + 1], s1);
    atomicAdd(&a4[(size_t)d * 64 + q], d0);
    atomicAdd(&a4[(size_t)d * 64 + q + 1], d1);
    atomicAdd(&t4[(size_t)d * 64 + q],
              make_float4(coef * h0.x, coef * h0.y, coef * h0.z, coef * h0.w));
    atomicAdd(&t4[(size_t)d * 64 + q + 1],
              make_float4(coef * h1.x, coef * h1.y, coef * h1.z, coef * h1.w));
}

// ---------------- fp32 -> bf16 hi/lo split helpers ----------------
__device__ __forceinline__ void split8(const float* v, uint4& hi4, uint4& lo4) {
    __nv_bfloat16 h[8], l[8];
#pragma unroll
    for (int t = 0; t < 8; t++) {
        h[t] = __float2bfloat16(v[t]);
        l[t] = __float2bfloat16(v[t] - __bfloat162float(h[t]));
    }
    hi4 = *reinterpret_cast<uint4*>(h);
    lo4 = *reinterpret_cast<uint4*>(l);
}

// A = [x_aug | h | t1] -> bf16 hi/lo; pad rows zero.
__global__ __launch_bounds__(256) void k_conv_A(const float* __restrict__ h) {
    int i = blockIdx.x * blockDim.x + threadIdx.x;   // over MPAD*96 chunks of 8
    if (i >= MPAD * 96) return;
    int row = i / 96;
    int c8 = i % 96;
    uint4 hi4, li4;
    if (row < NN) {
        const float4* srcp;
        int cc = c8 & 31;
        if (c8 < 32)       srcp = reinterpret_cast<const float4*>(g_xaug) + (size_t)row * 64 + cc * 2;
        else if (c8 < 64)  srcp = reinterpret_cast<const float4*>(h) + (size_t)row * 64 + cc * 2;
        else               srcp = reinterpret_cast<const float4*>(g_t1) + (size_t)row * 64 + cc * 2;
        float v[8];
        float4 a = srcp[0], b = srcp[1];
        v[0]=a.x; v[1]=a.y; v[2]=a.z; v[3]=a.w; v[4]=b.x; v[5]=b.y; v[6]=b.z; v[7]=b.w;
        split8(v, hi4, li4);
    } else {
        hi4 = make_uint4(0,0,0,0); li4 = hi4;
    }
    reinterpret_cast<uint4*>(g_Ah)[i] = hi4;
    reinterpret_cast<uint4*>(g_Al)[i] = li4;
}

// W transposed pack, gate-blocked: n = g*256 + j
__global__ __launch_bounds__(256) void k_conv_W(
    const float* __restrict__ Wi, const float* __restrict__ Wf,
    const float* __restrict__ Wg, const float* __restrict__ Wo,
    const float* __restrict__ Wci, const float* __restrict__ Wcf,
    const float* __restrict__ Wcg, const float* __restrict__ Wco)
{
    int i = blockIdx.x * blockDim.x + threadIdx.x;   // over NCOL*96
    if (i >= NCOL * 96) return;
    int n = i / 96;
    int kc = i % 96;
    int g = n >> 8, j = n & 255;
    const float* Win[4] = {Wi, Wf, Wg, Wo};
    const float* Wc[4]  = {Wci, Wcf, Wcg, Wco};
    float v[8];
#pragma unroll
    for (int t = 0; t < 8; t++) {
        int k = kc * 8 + t;
        if (k < 256)      v[t] = Win[g][k * 256 + j];
        else if (k < 512) v[t] = Wc[g][(k - 256) * 256 + j];
        else              v[t] = Wc[g][65536 + (k - 512) * 256 + j];
    }
    uint4 hi4, lo4;
    split8(v, hi4, lo4);
    reinterpret_cast<uint4*>(g_Wh)[i] = hi4;
    reinterpret_cast<uint4*>(g_Wl)[i] = lo4;
}

__global__ __launch_bounds__(256) void k_conv_Wlin(const float* __restrict__ Wlin) {
    int i = blockIdx.x * blockDim.x + threadIdx.x;   // over 256*32
    if (i >= HD * 32) return;
    int n = i / 32;
    int kc = i % 32;
    float v[8];
#pragma unroll
    for (int t = 0; t < 8; t++) v[t] = Wlin[(kc * 8 + t) * 256 + n];
    uint4 hi4, lo4;
    split8(v, hi4, lo4);
    reinterpret_cast<uint4*>(g_WlTh)[i] = hi4;
    reinterpret_cast<uint4*>(g_WlTl)[i] = lo4;
}

// ============ bf16-split GEMM via mma.sync (sm_80+ path) ============
// CTA tile 128x128x32, 4-stage cp.async pipeline, 8 warps (2x4), warp tile 64x32.
#define BKG   32
#define NSTG  4
#define TSTR  80                  // smem row stride bytes; 5x16B mod 8 => conflict-free ldmatrix
#define TILEB (128 * TSTR)
#define STAGEB (4 * TILEB)
#define SMEM_GEMM (NSTG * STAGEB) // 163840 B

__device__ __forceinline__ void cp16(uint32_t saddr, const void* gaddr) {
    asm volatile("cp.async.cg.shared.global [%0], [%1], 16;" :: "r"(saddr), "l"(gaddr));
}
__device__ __forceinline__ void ldm_x4(uint32_t* r, uint32_t a) {
    asm volatile("ldmatrix.sync.aligned.m8n8.x4.shared.b16 {%0,%1,%2,%3}, [%4];"
                 : "=r"(r[0]), "=r"(r[1]), "=r"(r[2]), "=r"(r[3]) : "r"(a));
}
__device__ __forceinline__ void ldm_x2(uint32_t* r, uint32_t a) {
    asm volatile("ldmatrix.sync.aligned.m8n8.x2.shared.b16 {%0,%1}, [%2];"
                 : "=r"(r[0]), "=r"(r[1]) : "r"(a));
}
__device__ __forceinline__ void mma16816(float* c, const uint32_t* a, const uint32_t* b) {
    asm volatile(
        "mma.sync.aligned.m16n8k16.row.col.f32.bf16.bf16.f32 "
        "{%0,%1,%2,%3}, {%4,%5,%6,%7}, {%8,%9}, {%0,%1,%2,%3};"
        : "+f"(c[0]), "+f"(c[1]), "+f"(c[2]), "+f"(c[3])
        : "r"(a[0]), "r"(a[1]), "r"(a[2]), "r"(a[3]), "r"(b[0]), "r"(b[1]));
}

__global__ __launch_bounds__(256) void k_mma(
    const __nv_bfloat16* __restrict__ Ah, const __nv_bfloat16* __restrict__ Al,
    const __nv_bfloat16* __restrict__ Bh, const __nv_bfloat16* __restrict__ Bl,
    float* __restrict__ C, int K, int Ncols, const float* __restrict__ bias, int m_limit)
{
    extern __shared__ char smem[];
    const int tid = threadIdx.x;
    const int wid = tid >> 5;
    const int lane = tid & 31;
    const int m0 = blockIdx.y * 128;
    const int n0 = blockIdx.x * 128;
    const int nkt = K / BKG;
    const uint32_t sb = smem_u32(smem);

    const int wr = (wid >> 2) * 64;
    const int wc = (wid & 3) * 32;

    const int r0c = tid >> 2, c0c = tid & 3;
    const int r1c = (tid + 256) >> 2, c1c = tid & 3;

    float acc[4][4][4] = {};

    auto issue_stage = [&](int kt, int buf) {
        uint32_t s = sb + buf * STAGEB;
        const char* ahB = reinterpret_cast<const char*>(Ah);
        const char* alB = reinterpret_cast<const char*>(Al);
        const char* bhB = reinterpret_cast<const char*>(Bh);
        const char* blB = reinterpret_cast<const char*>(Bl);
        size_t kb = (size_t)kt * BKG * 2;
        {
            size_t ga = ((size_t)(m0 + r0c) * K) * 2 + kb + c0c * 16;
            size_t gb = ((size_t)(n0 + r0c) * K) * 2 + kb + c0c * 16;
            uint32_t so = r0c * TSTR + c0c * 16;
            cp16(s + so, ahB + ga);
            cp16(s + TILEB + so, alB + ga);
            cp16(s + 2 * TILEB + so, bhB + gb);
            cp16(s + 3 * TILEB + so, blB + gb);
        }
        {
            size_t ga = ((size_t)(m0 + r1c) * K) * 2 + kb + c1c * 16;
            size_t gb = ((size_t)(n0 + r1c) * K) * 2 + kb + c1c * 16;
            uint32_t so = r1c * TSTR + c1c * 16;
            cp16(s + so, ahB + ga);
            cp16(s + TILEB + so, alB + ga);
            cp16(s + 2 * TILEB + so, bhB + gb);
            cp16(s + 3 * TILEB + so, blB + gb);
        }
    };

    for (int s = 0; s < NSTG - 1; s++) {
        if (s < nkt) issue_stage(s, s);
        asm volatile("cp.async.commit_group;");
    }

    for (int kt = 0; kt < nkt; kt++) {
        asm volatile("cp.async.wait_group %0;" :: "n"(NSTG - 2));
        __syncthreads();

        uint32_t s = sb + (kt % NSTG) * STAGEB;
        uint32_t sAh = s, sAl = s + TILEB, sBh = s + 2 * TILEB, sBl = s + 3 * TILEB;

#pragma unroll
        for (int ks = 0; ks < 2; ks++) {
            uint32_t ah[4][4], al[4][4], bh[4][2], bl[4][2];
            uint32_t aoff = (wr + (lane & 15)) * TSTR + ks * 32 + ((lane >> 4) & 1) * 16;
#pragma unroll
            for (int mt = 0; mt < 4; mt++) {
                ldm_x4(ah[mt], sAh + aoff + mt * 16 * TSTR);
                ldm_x4(al[mt], sAl + aoff + mt * 16 * TSTR);
            }
            int l = lane & 15;
            uint32_t boff = (wc + (l & 7)) * TSTR + ks * 32 + ((l >> 3) & 1) * 16;
#pragma unroll
            for (int nt = 0; nt < 4; nt++) {
                ldm_x2(bh[nt], sBh + boff + nt * 8 * TSTR);
                ldm_x2(bl[nt], sBl + boff + nt * 8 * TSTR);
            }
#pragma unroll
            for (int mt = 0; mt < 4; mt++)
#pragma unroll
                for (int nt = 0; nt < 4; nt++) {
                    mma16816(acc[mt][nt], ah[mt], bh[nt]);
                    mma16816(acc[mt][nt], ah[mt], bl[nt]);
                    mma16816(acc[mt][nt], al[mt], bh[nt]);
                }
        }
        __syncthreads();
        int nk = kt + NSTG - 1;
        if (nk < nkt) issue_stage(nk, nk % NSTG);
        asm volatile("cp.async.commit_group;");
    }

    // epilogue: direct register -> gmem
#pragma unroll
    for (int mt = 0; mt < 4; mt++) {
        int rA = m0 + wr + mt * 16 + (lane >> 2);
        int rB = rA + 8;
#pragma unroll
        for (int nt = 0; nt < 4; nt++) {
            int col = n0 + wc + nt * 8 + (lane & 3) * 2;
            float bx = 0.f, by = 0.f;
            if (bias) { bx = bias[col]; by = bias[col + 1]; }
            if (rA < m_limit) {
                float2 v = make_float2(acc[mt][nt][0] + bx, acc[mt][nt][1] + by);
                *reinterpret_cast<float2*>(C + (size_t)rA * Ncols + col) = v;
            }
            if (rB < m_limit) {
                float2 v = make_float2(acc[mt][nt][2] + bx, acc[mt][nt][3] + by);
                *reinterpret_cast<float2*>(C + (size_t)rB * Ncols + col) = v;
            }
        }
    }
}

// ---------------- gates: h0, c_new, relu split ----------------
__global__ __launch_bounds__(256) void k_gates(
    const float* __restrict__ c,
    const float* __restrict__ bci, const float* __restrict__ bcf,
    const float* __restrict__ bcg, const float* __restrict__ bco,
    const float* __restrict__ bi, const float* __restrict__ bf,
    const float* __restrict__ bg, const float* __restrict__ bo,
    const float* __restrict__ wci, const float* __restrict__ wcf,
    const float* __restrict__ wco,
    float* __restrict__ out)
{
    int idx = blockIdx.x * blockDim.x + threadIdx.x;
    if (idx >= MPAD * HD) return;
    int row = idx >> 8;
    int j = idx & 255;
    if (row >= NN) {
        g_Rh[idx] = __float2bfloat16(0.f);
        g_Rl[idx] = __float2bfloat16(0.f);
        return;
    }
    const float* z = g_Z + (size_t)row * NCOL;
    float cv = c[idx];
    float ig = sigf(z[j]       + bci[j] + bi[j] + wci[j] * cv);
    float fg = sigf(z[256 + j] + bcf[j] + bf[j] + wcf[j] * cv);
    float gg = tanhf(z[512 + j] + bcg[j] + bg[j]);
    float cn = fg * cv + ig * gg;
    float og = sigf(z[768 + j] + bco[j] + bo[j] + wco[j] * cn);
    float h0 = og * tanhf(cn);
    out[NH + idx]     = h0;
    out[2 * NH + idx] = cn;
    float r = fmaxf(h0, 0.f);
    __nv_bfloat16 rh = __float2bfloat16(r);
    __nv_bfloat16 rl = __float2bfloat16(r - __bfloat162float(rh));
    g_Rh[idx] = rh;
    g_Rl[idx] = rl;
}

// ---------------- launch ----------------
extern "C" void kernel_launch(void* const* d_in, const int* in_sizes, int n_in,
                              void* d_out, int out_size) {
    const float* x    = (const float*)d_in[0];
    const int*   ei   = (const int*)d_in[1];
    const float* ew   = (const float*)d_in[2];
    const float* h    = (const float*)d_in[3];
    const float* c    = (const float*)d_in[4];
    const int*   snid = (const int*)d_in[5];
    const int*   dnid = (const int*)d_in[6];
    const float* Wi   = (const float*)d_in[7];
    const float* Wf   = (const float*)d_in[8];
    const float* Wg   = (const float*)d_in[9];
    const float* Wo   = (const float*)d_in[10];
    const float* Wci  = (const float*)d_in[11];
    const float* Wcf  = (const float*)d_in[12];
    const float* Wcg  = (const float*)d_in[13];
    const float* Wco  = (const float*)d_in[14];
    const float* bci  = (const float*)d_in[15];
    const float* bcf  = (const float*)d_in[16];
    const float* bcg  = (const float*)d_in[17];
    const float* bco  = (const float*)d_in[18];

    const float *bi, *bf, *bg, *bo, *blin, *wci, *wcf, *wco, *Wlin;
    if (in_sizes[27] == 65536) {
        bi = (const float*)d_in[19]; bf = (const float*)d_in[20];
        bg = (const float*)d_in[21]; bo = (const float*)d_in[22];
        blin = (const float*)d_in[23];
        wci = (const float*)d_in[24]; wcf = (const float*)d_in[25];
        wco = (const float*)d_in[26];
        Wlin = (const float*)d_in[27];
    } else {
        wci = (const float*)d_in[19]; wcf = (const float*)d_in[20];
        wco = (const float*)d_in[21];
        bi = (const float*)d_in[22]; bf = (const float*)d_in[23];
        bg = (const float*)d_in[24]; bo = (const float*)d_in[25];
        Wlin = (const float*)d_in[26];
        blin = (const float*)d_in[27];
    }

    const int* src = ei;
    const int* dst = ei + NE;
    float* out = (float*)d_out;

    cudaFuncSetAttribute(k_mma, cudaFuncAttributeMaxDynamicSharedMemorySize, SMEM_GEMM);

    k_init<<<(NN * 64 + 255) / 256, 256>>>(x);
    k_conv_W<<<(NCOL * 96 + 255) / 256, 256>>>(Wi, Wf, Wg, Wo, Wci, Wcf, Wcg, Wco);
    k_conv_Wlin<<<(HD * 32 + 255) / 256, 256>>>(Wlin);
    k_deg<<<(NE + 255) / 256, 256>>>(src, ew);
    k_dinv<<<(NN + 255) / 256, 256>>>();
    k_edge<<<(NE * 32) / 256, 256>>>(x, h, src, dst, snid, dnid, ew);
    k_conv_A<<<(MPAD * 96 + 255) / 256, 256>>>(h);

    float *Ah, *Al, *Wh, *Wl, *Zp, *Rh, *Rl, *WlTh, *WlTl;
    cudaGetSymbolAddress((void**)&Ah, g_Ah);
    cudaGetSymbolAddress((void**)&Al, g_Al);
    cudaGetSymbolAddress((void**)&Wh, g_Wh);
    cudaGetSymbolAddress((void**)&Wl, g_Wl);
    cudaGetSymbolAddress((void**)&Zp, g_Z);
    cudaGetSymbolAddress((void**)&Rh, g_Rh);
    cudaGetSymbolAddress((void**)&Rl, g_Rl);
    cudaGetSymbolAddress((void**)&WlTh, g_WlTh);
    cudaGetSymbolAddress((void**)&WlTl, g_WlTl);

    // big GEMM: Z[MPAD x 1024] = A @ W^T
    {
        dim3 grid(NCOL / 128, MPAD / 128);
        k_mma<<<grid, 256, SMEM_GEMM>>>(
            (const __nv_bfloat16*)Ah, (const __nv_bfloat16*)Al,
            (const __nv_bfloat16*)Wh, (const __nv_bfloat16*)Wl,
            Zp, KTOT, NCOL, nullptr, MPAD);
    }

    k_gates<<<(MPAD * HD + 255) / 256, 256>>>(c, bci, bcf, bcg, bco, bi, bf, bg, bo,
                                              wci, wcf, wco, out);

    // small GEMM: h_out[NN x 256] = relu(h0) @ W_lin + b_lin
    {
        dim3 grid(HD / 128, MPAD / 128);
        k_mma<<<grid, 256, SMEM_GEMM>>>(
            (const __nv_bfloat16*)Rh, (const __nv_bfloat16*)Rl,
            (const __nv_bfloat16*)WlTh, (const __nv_bfloat16*)WlTl,
            out, HD, HD, blin, NN);
    }
}

// round 8
// speedup vs baseline: 1.4634x; 1.2661x over previous
#include <cuda_runtime.h>
#include <cuda_bf16.h>
#include <math.h>
#include <stdint.h>

// Problem constants
#define NN    30000
#define NE    480000
#define HD    256
#define MPAD  30080      // 235*128
#define KTOT  768        // x_aug | h | t1
#define NCOL  1024       // 4 gates * 256 (gate-blocked: col = g*256 + j)
#define NH    (NN * HD)

// ---------------- static device scratch ----------------
__device__ float g_deg[NN];                       // degree -> dinv in place
__device__ float g_norm[NE];                      // per-edge cheb coefficient
__device__ int   g_cnt_src[NN], g_cnt_dst[NN];    // bucket counts
__device__ int   g_off_src[NN], g_off_dst[NN];    // bucket offsets (exclusive)
__device__ int   g_cur_src[NN], g_cur_dst[NN];    // fill cursors
__device__ int   g_eid_src[NE], g_eid_dst[NE];    // edge ids bucketed
__device__ float g_Z[MPAD * NCOL];                // gate pre-activations (fp32)
__device__ __align__(16) __nv_bfloat16 g_Ah[MPAD * KTOT];   // pad rows stay 0 (static zero-init, never written)
__device__ __align__(16) __nv_bfloat16 g_Al[MPAD * KTOT];
__device__ __align__(16) __nv_bfloat16 g_Wh[NCOL * KTOT];   // W transposed: [n][k]
__device__ __align__(16) __nv_bfloat16 g_Wl[NCOL * KTOT];
__device__ __align__(16) __nv_bfloat16 g_Rh[MPAD * HD];     // relu(h0) split
__device__ __align__(16) __nv_bfloat16 g_Rl[MPAD * HD];
__device__ __align__(16) __nv_bfloat16 g_WlTh[HD * HD];
__device__ __align__(16) __nv_bfloat16 g_WlTl[HD * HD];

__device__ __forceinline__ float sigf(float x) { return 1.0f / (1.0f + expf(-x)); }

__device__ __forceinline__ uint32_t smem_u32(const void* p) {
    uint32_t a;
    asm("{ .reg .u64 t; cvta.to.shared.u64 t, %1; cvt.u32.u64 %0, t; }" : "=r"(a) : "l"(p));
    return a;
}

// ---------------- CSR build ----------------
__global__ __launch_bounds__(256) void k_zero() {
    int i = blockIdx.x * blockDim.x + threadIdx.x;
    if (i < NN) { g_cnt_src[i] = 0; g_cnt_dst[i] = 0; g_deg[i] = 0.f; }
}

__global__ __launch_bounds__(256) void k_count(const int* __restrict__ src,
                                               const int* __restrict__ dst,
                                               const float* __restrict__ ew) {
    int e = blockIdx.x * blockDim.x + threadIdx.x;
    if (e < NE) {
        int s = src[e], d = dst[e];
        atomicAdd(&g_cnt_src[s], 1);
        atomicAdd(&g_cnt_dst[d], 1);
        atomicAdd(&g_deg[s], ew[e]);
    }
}

__global__ __launch_bounds__(256) void k_dinv() {
    int i = blockIdx.x * blockDim.x + threadIdx.x;
    if (i < NN) {
        float d = g_deg[i];
        g_deg[i] = (d > 0.f) ? rsqrtf(fmaxf(d, 1e-12f)) : 0.f;
    }
}

// single-block exclusive scan of both count arrays -> offsets + cursors
#define SCH 30   // 1024*30 = 30720 >= NN
__global__ __launch_bounds__(1024) void k_scan() {
    __shared__ int sh[1024];
    int t = threadIdx.x;
    int base = t * SCH;
#pragma unroll 1
    for (int pass = 0; pass < 2; pass++) {
        const int* cnt = pass ? g_cnt_dst : g_cnt_src;
        int* off = pass ? g_off_dst : g_off_src;
        int* cur = pass ? g_cur_dst : g_cur_src;
        int local = 0;
        for (int i = 0; i < SCH; i++) {
            int idx = base + i;
            if (idx < NN) local += cnt[idx];
        }
        sh[t] = local;
        __syncthreads();
        for (int o = 1; o < 1024; o <<= 1) {
            int v = 0;
            if (t >= o) v = sh[t - o];
            __syncthreads();
            if (t >= o) sh[t] += v;
            __syncthreads();
        }
        int run = (t > 0) ? sh[t - 1] : 0;
        for (int i = 0; i < SCH; i++) {
            int idx = base + i;
            if (idx < NN) {
                off[idx] = run;
                cur[idx] = run;
                run += cnt[idx];
            }
        }
        __syncthreads();
    }
}

__global__ __launch_bounds__(256) void k_fill(const int* __restrict__ src,
                                              const int* __restrict__ dst,
                                              const float* __restrict__ ew) {
    int e = blockIdx.x * blockDim.x + threadIdx.x;
    if (e < NE) {
        int s = src[e], d = dst[e];
        g_norm[e] = -g_deg[s] * ew[e] * g_deg[d];
        int ps = atomicAdd(&g_cur_src[s], 1);
        g_eid_src[ps] = e;
        int pd = atomicAdd(&g_cur_dst[d], 1);
        g_eid_dst[pd] = e;
    }
}

// ---------------- fp32 -> bf16 hi/lo split ----------------
__device__ __forceinline__ void split4(float4 v, uint2& hi, uint2& lo) {
    __nv_bfloat16 h[4], l[4];
    float f[4] = {v.x, v.y, v.z, v.w};
#pragma unroll
    for (int t = 0; t < 4; t++) {
        h[t] = __float2bfloat16(f[t]);
        l[t] = __float2bfloat16(f[t] - __bfloat162float(h[t]));
    }
    hi = *reinterpret_cast<uint2*>(h);
    lo = *reinterpret_cast<uint2*>(l);
}

// ---------------- gather + pack A: per node, no FP atomics ----------------
// 4 nodes per 256-thread block; 64 threads per node; thread t owns float4 #t of the row.
__global__ __launch_bounds__(256) void k_gatherA(
    const float* __restrict__ x, const float* __restrict__ h,
    const int* __restrict__ src,
    const int* __restrict__ snid, const int* __restrict__ dnid)
{
    int node = blockIdx.x * 4 + (threadIdx.x >> 6);
    int t = threadIdx.x & 63;
    if (node >= NN) return;

    const float4* x4 = reinterpret_cast<const float4*>(x);
    const float4* h4 = reinterpret_cast<const float4*>(h);

    float4 ax = x4[(size_t)node * 64 + t];
    float4 at = make_float4(0.f, 0.f, 0.f, 0.f);

    {
        int o = g_off_src[node], c = g_cnt_src[node];
        for (int i = 0; i < c; i++) {
            int e = g_eid_src[o + i];
            int sn = snid[e];
            float4 v = x4[(size_t)sn * 64 + t];
            ax.x += v.x; ax.y += v.y; ax.z += v.z; ax.w += v.w;
        }
    }
    {
        int o = g_off_dst[node], c = g_cnt_dst[node];
        for (int i = 0; i < c; i++) {
            int e = g_eid_dst[o + i];
            int dn = dnid[e];
            float4 v = x4[(size_t)dn * 64 + t];
            ax.x += v.x; ax.y += v.y; ax.z += v.z; ax.w += v.w;
            float nm = g_norm[e];
            int s = src[e];
            float4 hv = h4[(size_t)s * 64 + t];
            at.x += nm * hv.x; at.y += nm * hv.y; at.z += nm * hv.z; at.w += nm * hv.w;
        }
    }

    float4 hr = h4[(size_t)node * 64 + t];

    uint2 hi, lo;
    size_t rb = (size_t)node * KTOT;
    split4(ax, hi, lo);
    *reinterpret_cast<uint2*>(g_Ah + rb + t * 4) = hi;
    *reinterpret_cast<uint2*>(g_Al + rb + t * 4) = lo;
    split4(hr, hi, lo);
    *reinterpret_cast<uint2*>(g_Ah + rb + 256 + t * 4) = hi;
    *reinterpret_cast<uint2*>(g_Al + rb + 256 + t * 4) = lo;
    split4(at, hi, lo);
    *reinterpret_cast<uint2*>(g_Ah + rb + 512 + t * 4) = hi;
    *reinterpret_cast<uint2*>(g_Al + rb + 512 + t * 4) = lo;
}

// ---------------- weight packs ----------------
__device__ __forceinline__ void split8(const float* v, uint4& hi4, uint4& lo4) {
    __nv_bfloat16 h[8], l[8];
#pragma unroll
    for (int t = 0; t < 8; t++) {
        h[t] = __float2bfloat16(v[t]);
        l[t] = __float2bfloat16(v[t] - __bfloat162float(h[t]));
    }
    hi4 = *reinterpret_cast<uint4*>(h);
    lo4 = *reinterpret_cast<uint4*>(l);
}

__global__ __launch_bounds__(256) void k_conv_W(
    const float* __restrict__ Wi, const float* __restrict__ Wf,
    const float* __restrict__ Wg, const float* __restrict__ Wo,
    const float* __restrict__ Wci, const float* __restrict__ Wcf,
    const float* __restrict__ Wcg, const float* __restrict__ Wco)
{
    int i = blockIdx.x * blockDim.x + threadIdx.x;   // over NCOL*96
    if (i >= NCOL * 96) return;
    int n = i / 96;
    int kc = i % 96;
    int g = n >> 8, j = n & 255;
    const float* Win[4] = {Wi, Wf, Wg, Wo};
    const float* Wc[4]  = {Wci, Wcf, Wcg, Wco};
    float v[8];
#pragma unroll
    for (int t = 0; t < 8; t++) {
        int k = kc * 8 + t;
        if (k < 256)      v[t] = Win[g][k * 256 + j];
        else if (k < 512) v[t] = Wc[g][(k - 256) * 256 + j];
        else              v[t] = Wc[g][65536 + (k - 512) * 256 + j];
    }
    uint4 hi4, lo4;
    split8(v, hi4, lo4);
    reinterpret_cast<uint4*>(g_Wh)[i] = hi4;
    reinterpret_cast<uint4*>(g_Wl)[i] = lo4;
}

__global__ __launch_bounds__(256) void k_conv_Wlin(const float* __restrict__ Wlin) {
    int i = blockIdx.x * blockDim.x + threadIdx.x;   // over 256*32
    if (i >= HD * 32) return;
    int n = i / 32;
    int kc = i % 32;
    float v[8];
#pragma unroll
    for (int t = 0; t < 8; t++) v[t] = Wlin[(kc * 8 + t) * 256 + n];
    uint4 hi4, lo4;
    split8(v, hi4, lo4);
    reinterpret_cast<uint4*>(g_WlTh)[i] = hi4;
    reinterpret_cast<uint4*>(g_WlTl)[i] = lo4;
}

// ============ bf16-split GEMM via mma.sync (exact R3 config: NSTG=3) ============
#define BKG   32
#define NSTG  3
#define TSTR  80
#define TILEB (128 * TSTR)
#define STAGEB (4 * TILEB)
#define SMEM_GEMM (NSTG * STAGEB)

__device__ __forceinline__ void cp16(uint32_t saddr, const void* gaddr) {
    asm volatile("cp.async.cg.shared.global [%0], [%1], 16;" :: "r"(saddr), "l"(gaddr));
}
__device__ __forceinline__ void ldm_x4(uint32_t* r, uint32_t a) {
    asm volatile("ldmatrix.sync.aligned.m8n8.x4.shared.b16 {%0,%1,%2,%3}, [%4];"
                 : "=r"(r[0]), "=r"(r[1]), "=r"(r[2]), "=r"(r[3]) : "r"(a));
}
__device__ __forceinline__ void ldm_x2(uint32_t* r, uint32_t a) {
    asm volatile("ldmatrix.sync.aligned.m8n8.x2.shared.b16 {%0,%1}, [%2];"
                 : "=r"(r[0]), "=r"(r[1]) : "r"(a));
}
__device__ __forceinline__ void mma16816(float* c, const uint32_t* a, const uint32_t* b) {
    asm volatile(
        "mma.sync.aligned.m16n8k16.row.col.f32.bf16.bf16.f32 "
        "{%0,%1,%2,%3}, {%4,%5,%6,%7}, {%8,%9}, {%0,%1,%2,%3};"
        : "+f"(c[0]), "+f"(c[1]), "+f"(c[2]), "+f"(c[3])
        : "r"(a[0]), "r"(a[1]), "r"(a[2]), "r"(a[3]), "r"(b[0]), "r"(b[1]));
}

__global__ __launch_bounds__(256) void k_mma(
    const __nv_bfloat16* __restrict__ Ah, const __nv_bfloat16* __restrict__ Al,
    const __nv_bfloat16* __restrict__ Bh, const __nv_bfloat16* __restrict__ Bl,
    float* __restrict__ C, int K, int Ncols, const float* __restrict__ bias, int m_limit)
{
    extern __shared__ char smem[];
    const int tid = threadIdx.x;
    const int wid = tid >> 5;
    const int lane = tid & 31;
    const int m0 = blockIdx.y * 128;
    const int n0 = blockIdx.x * 128;
    const int nkt = K / BKG;
    const uint32_t sb = smem_u32(smem);

    const int wr = (wid >> 2) * 64;
    const int wc = (wid & 3) * 32;

    const int r0c = tid >> 2, c0c = tid & 3;
    const int r1c = (tid + 256) >> 2, c1c = tid & 3;

    float acc[4][4][4] = {};

    auto issue_stage = [&](int kt, int buf) {
        uint32_t s = sb + buf * STAGEB;
        const char* ahB = reinterpret_cast<const char*>(Ah);
        const char* alB = reinterpret_cast<const char*>(Al);
        const char* bhB = reinterpret_cast<const char*>(Bh);
        const char* blB = reinterpret_cast<const char*>(Bl);
        size_t kb = (size_t)kt * BKG * 2;
        {
            size_t ga = ((size_t)(m0 + r0c) * K) * 2 + kb + c0c * 16;
            size_t gb = ((size_t)(n0 + r0c) * K) * 2 + kb + c0c * 16;
            uint32_t so = r0c * TSTR + c0c * 16;
            cp16(s + so, ahB + ga);
            cp16(s + TILEB + so, alB + ga);
            cp16(s + 2 * TILEB + so, bhB + gb);
            cp16(s + 3 * TILEB + so, blB + gb);
        }
        {
            size_t ga = ((size_t)(m0 + r1c) * K) * 2 + kb + c1c * 16;
            size_t gb = ((size_t)(n0 + r1c) * K) * 2 + kb + c1c * 16;
            uint32_t so = r1c * TSTR + c1c * 16;
            cp16(s + so, ahB + ga);
            cp16(s + TILEB + so, alB + ga);
            cp16(s + 2 * TILEB + so, bhB + gb);
            cp16(s + 3 * TILEB + so, blB + gb);
        }
    };

    for (int s = 0; s < NSTG - 1; s++) {
        if (s < nkt) issue_stage(s, s);
        asm volatile("cp.async.commit_group;");
    }

    for (int kt = 0; kt < nkt; kt++) {
        asm volatile("cp.async.wait_group %0;" :: "n"(NSTG - 2));
        __syncthreads();

        uint32_t s = sb + (kt % NSTG) * STAGEB;
        uint32_t sAh = s, sAl = s + TILEB, sBh = s + 2 * TILEB, sBl = s + 3 * TILEB;

#pragma unroll
        for (int ks = 0; ks < 2; ks++) {
            uint32_t ah[4][4], al[4][4], bh[4][2], bl[4][2];
            uint32_t aoff = (wr + (lane & 15)) * TSTR + ks * 32 + ((lane >> 4) & 1) * 16;
#pragma unroll
            for (int mt = 0; mt < 4; mt++) {
                ldm_x4(ah[mt], sAh + aoff + mt * 16 * TSTR);
                ldm_x4(al[mt], sAl + aoff + mt * 16 * TSTR);
            }
            int l = lane & 15;
            uint32_t boff = (wc + (l & 7)) * TSTR + ks * 32 + ((l >> 3) & 1) * 16;
#pragma unroll
            for (int nt = 0; nt < 4; nt++) {
                ldm_x2(bh[nt], sBh + boff + nt * 8 * TSTR);
                ldm_x2(bl[nt], sBl + boff + nt * 8 * TSTR);
            }
#pragma unroll
            for (int mt = 0; mt < 4; mt++)
#pragma unroll
                for (int nt = 0; nt < 4; nt++) {
                    mma16816(acc[mt][nt], ah[mt], bh[nt]);
                    mma16816(acc[mt][nt], ah[mt], bl[nt]);
                    mma16816(acc[mt][nt], al[mt], bh[nt]);
                }
        }
        __syncthreads();
        int nk = kt + NSTG - 1;
        if (nk < nkt) issue_stage(nk, nk % NSTG);
        asm volatile("cp.async.commit_group;");
    }

#pragma unroll
    for (int mt = 0; mt < 4; mt++) {
        int rA = m0 + wr + mt * 16 + (lane >> 2);
        int rB = rA + 8;
#pragma unroll
        for (int nt = 0; nt < 4; nt++) {
            int col = n0 + wc + nt * 8 + (lane & 3) * 2;
            float bx = 0.f, by = 0.f;
            if (bias) { bx = bias[col]; by = bias[col + 1]; }
            if (rA < m_limit) {
                float2 v = make_float2(acc[mt][nt][0] + bx, acc[mt][nt][1] + by);
                *reinterpret_cast<float2*>(C + (size_t)rA * Ncols + col) = v;
            }
            if (rB < m_limit) {
                float2 v = make_float2(acc[mt][nt][2] + bx, acc[mt][nt][3] + by);
                *reinterpret_cast<float2*>(C + (size_t)rB * Ncols + col) = v;
            }
        }
    }
}

// ---------------- gates: h0, c_new, relu split ----------------
__global__ __launch_bounds__(256) void k_gates(
    const float* __restrict__ c,
    const float* __restrict__ bci, const float* __restrict__ bcf,
    const float* __restrict__ bcg, const float* __restrict__ bco,
    const float* __restrict__ bi, const float* __restrict__ bf,
    const float* __restrict__ bg, const float* __restrict__ bo,
    const float* __restrict__ wci, const float* __restrict__ wcf,
    const float* __restrict__ wco,
    float* __restrict__ out)
{
    int idx = blockIdx.x * blockDim.x + threadIdx.x;
    if (idx >= MPAD * HD) return;
    int row = idx >> 8;
    int j = idx & 255;
    if (row >= NN) {
        g_Rh[idx] = __float2bfloat16(0.f);
        g_Rl[idx] = __float2bfloat16(0.f);
        return;
    }
    const float* z = g_Z + (size_t)row * NCOL;
    float cv = c[idx];
    float ig = sigf(z[j]       + bci[j] + bi[j] + wci[j] * cv);
    float fg = sigf(z[256 + j] + bcf[j] + bf[j] + wcf[j] * cv);
    float gg = tanhf(z[512 + j] + bcg[j] + bg[j]);
    float cn = fg * cv + ig * gg;
    float og = sigf(z[768 + j] + bco[j] + bo[j] + wco[j] * cn);
    float h0 = og * tanhf(cn);
    out[NH + idx]     = h0;
    out[2 * NH + idx] = cn;
    float r = fmaxf(h0, 0.f);
    __nv_bfloat16 rh = __float2bfloat16(r);
    __nv_bfloat16 rl = __float2bfloat16(r - __bfloat162float(rh));
    g_Rh[idx] = rh;
    g_Rl[idx] = rl;
}

// ---------------- launch ----------------
extern "C" void kernel_launch(void* const* d_in, const int* in_sizes, int n_in,
                              void* d_out, int out_size) {
    const float* x    = (const float*)d_in[0];
    const int*   ei   = (const int*)d_in[1];
    const float* ew   = (const float*)d_in[2];
    const float* h    = (const float*)d_in[3];
    const float* c    = (const float*)d_in[4];
    const int*   snid = (const int*)d_in[5];
    const int*   dnid = (const int*)d_in[6];
    const float* Wi   = (const float*)d_in[7];
    const float* Wf   = (const float*)d_in[8];
    const float* Wg   = (const float*)d_in[9];
    const float* Wo   = (const float*)d_in[10];
    const float* Wci  = (const float*)d_in[11];
    const float* Wcf  = (const float*)d_in[12];
    const float* Wcg  = (const float*)d_in[13];
    const float* Wco  = (const float*)d_in[14];
    const float* bci  = (const float*)d_in[15];
    const float* bcf  = (const float*)d_in[16];
    const float* bcg  = (const float*)d_in[17];
    const float* bco  = (const float*)d_in[18];

    const float *bi, *bf, *bg, *bo, *blin, *wci, *wcf, *wco, *Wlin;
    if (in_sizes[27] == 65536) {
        bi = (const float*)d_in[19]; bf = (const float*)d_in[20];
        bg = (const float*)d_in[21]; bo = (const float*)d_in[22];
        blin = (const float*)d_in[23];
        wci = (const float*)d_in[24]; wcf = (const float*)d_in[25];
        wco = (const float*)d_in[26];
        Wlin = (const float*)d_in[27];
    } else {
        wci = (const float*)d_in[19]; wcf = (const float*)d_in[20];
        wco = (const float*)d_in[21];
        bi = (const float*)d_in[22]; bf = (const float*)d_in[23];
        bg = (const float*)d_in[24]; bo = (const float*)d_in[25];
        Wlin = (const float*)d_in[26];
        blin = (const float*)d_in[27];
    }

    const int* src = ei;
    const int* dst = ei + NE;
    float* out = (float*)d_out;

    cudaFuncSetAttribute(k_mma, cudaFuncAttributeMaxDynamicSharedMemorySize, SMEM_GEMM);

    // CSR build + weight packs (packs overlap the build on the same stream queue)
    k_zero<<<(NN + 255) / 256, 256>>>();
    k_conv_W<<<(NCOL * 96 + 255) / 256, 256>>>(Wi, Wf, Wg, Wo, Wci, Wcf, Wcg, Wco);
    k_conv_Wlin<<<(HD * 32 + 255) / 256, 256>>>(Wlin);
    k_count<<<(NE + 255) / 256, 256>>>(src, dst, ew);
    k_dinv<<<(NN + 255) / 256, 256>>>();
    k_scan<<<1, 1024>>>();
    k_fill<<<(NE + 255) / 256, 256>>>(src, dst, ew);

    // gather + pack A directly (no scatters, no conv_A)
    k_gatherA<<<(NN + 3) / 4, 256>>>(x, h, src, snid, dnid);

    float *Ah, *Al, *Wh, *Wl, *Zp, *Rh, *Rl, *WlTh, *WlTl;
    cudaGetSymbolAddress((void**)&Ah, g_Ah);
    cudaGetSymbolAddress((void**)&Al, g_Al);
    cudaGetSymbolAddress((void**)&Wh, g_Wh);
    cudaGetSymbolAddress((void**)&Wl, g_Wl);
    cudaGetSymbolAddress((void**)&Zp, g_Z);
    cudaGetSymbolAddress((void**)&Rh, g_Rh);
    cudaGetSymbolAddress((void**)&Rl, g_Rl);
    cudaGetSymbolAddress((void**)&WlTh, g_WlTh);
    cudaGetSymbolAddress((void**)&WlTl, g_WlTl);

    // big GEMM: Z[MPAD x 1024] = A @ W^T
    {
        dim3 grid(NCOL / 128, MPAD / 128);
        k_mma<<<grid, 256, SMEM_GEMM>>>(
            (const __nv_bfloat16*)Ah, (const __nv_bfloat16*)Al,
            (const __nv_bfloat16*)Wh, (const __nv_bfloat16*)Wl,
            Zp, KTOT, NCOL, nullptr, MPAD);
    }

    k_gates<<<(MPAD * HD + 255) / 256, 256>>>(c, bci, bcf, bcg, bco, bi, bf, bg, bo,
                                              wci, wcf, wco, out);

    // small GEMM: h_out[NN x 256] = relu(h0) @ W_lin + b_lin
    {
        dim3 grid(HD / 128, MPAD / 128);
        k_mma<<<grid, 256, SMEM_GEMM>>>(
            (const __nv_bfloat16*)Rh, (const __nv_bfloat16*)Rl,
            (const __nv_bfloat16*)WlTh, (const __nv_bfloat16*)WlTl,
            out, HD, HD, blin, NN);
    }
}

// round 9
// speedup vs baseline: 1.5154x; 1.0356x over previous
#include <cuda_runtime.h>
#include <cuda_bf16.h>
#include <math.h>
#include <stdint.h>

// Problem constants
#define NN    30000
#define NE    480000
#define HD    256
#define MPAD  30080      // 235*128
#define KTOT  768        // x_aug | h | t1
#define NCOL  1024       // 4 gates * 256 (gate-blocked: col = g*256 + j)
#define NH    (NN * HD)

// ---------------- static device scratch ----------------
__device__ float g_deg[NN];                       // degree -> dinv in place
__device__ int   g_cnt_src[NN], g_cnt_dst[NN];    // bucket counts
__device__ int   g_off_src[NN], g_off_dst[NN];    // bucket offsets (exclusive)
__device__ int   g_cur_src[NN], g_cur_dst[NN];    // fill cursors
__device__ int   g_nbr_src[NE];                   // resolved: snid[e] bucketed by src
__device__ int   g_nbr_dst[NE];                   // resolved: dnid[e] bucketed by dst
__device__ int   g_hsrc[NE];                      // resolved: src[e]  bucketed by dst
__device__ float g_nrm[NE];                       // resolved: norm_e  bucketed by dst
__device__ float g_Z[MPAD * NCOL];                // gate pre-activations (fp32)
__device__ __align__(16) __nv_bfloat16 g_Ah[MPAD * KTOT];   // pad rows stay 0 (static zero-init, never written)
__device__ __align__(16) __nv_bfloat16 g_Al[MPAD * KTOT];
__device__ __align__(16) __nv_bfloat16 g_Wh[NCOL * KTOT];   // W transposed: [n][k]
__device__ __align__(16) __nv_bfloat16 g_Wl[NCOL * KTOT];
__device__ __align__(16) __nv_bfloat16 g_Rh[MPAD * HD];     // relu(h0) split
__device__ __align__(16) __nv_bfloat16 g_Rl[MPAD * HD];
__device__ __align__(16) __nv_bfloat16 g_WlTh[HD * HD];
__device__ __align__(16) __nv_bfloat16 g_WlTl[HD * HD];

__device__ __forceinline__ float sigf(float x) { return 1.0f / (1.0f + expf(-x)); }

__device__ __forceinline__ uint32_t smem_u32(const void* p) {
    uint32_t a;
    asm("{ .reg .u64 t; cvta.to.shared.u64 t, %1; cvt.u32.u64 %0, t; }" : "=r"(a) : "l"(p));
    return a;
}

// ---------------- CSR build ----------------
__global__ __launch_bounds__(256) void k_zero() {
    int i = blockIdx.x * blockDim.x + threadIdx.x;
    if (i < NN) { g_cnt_src[i] = 0; g_cnt_dst[i] = 0; g_deg[i] = 0.f; }
}

__global__ __launch_bounds__(256) void k_count(const int* __restrict__ src,
                                               const int* __restrict__ dst,
                                               const float* __restrict__ ew) {
    int e = blockIdx.x * blockDim.x + threadIdx.x;
    if (e < NE) {
        int s = src[e], d = dst[e];
        atomicAdd(&g_cnt_src[s], 1);
        atomicAdd(&g_cnt_dst[d], 1);
        atomicAdd(&g_deg[s], ew[e]);
    }
}

__global__ __launch_bounds__(256) void k_dinv() {
    int i = blockIdx.x * blockDim.x + threadIdx.x;
    if (i < NN) {
        float d = g_deg[i];
        g_deg[i] = (d > 0.f) ? rsqrtf(fmaxf(d, 1e-12f)) : 0.f;
    }
}

// single-block exclusive scan of both count arrays -> offsets + cursors
#define SCH 30   // 1024*30 = 30720 >= NN
__global__ __launch_bounds__(1024) void k_scan() {
    __shared__ int sh[1024];
    int t = threadIdx.x;
    int base = t * SCH;
#pragma unroll 1
    for (int pass = 0; pass < 2; pass++) {
        const int* cnt = pass ? g_cnt_dst : g_cnt_src;
        int* off = pass ? g_off_dst : g_off_src;
        int* cur = pass ? g_cur_dst : g_cur_src;
        int local = 0;
        for (int i = 0; i < SCH; i++) {
            int idx = base + i;
            if (idx < NN) local += cnt[idx];
        }
        sh[t] = local;
        __syncthreads();
        for (int o = 1; o < 1024; o <<= 1) {
            int v = 0;
            if (t >= o) v = sh[t - o];
            __syncthreads();
            if (t >= o) sh[t] += v;
            __syncthreads();
        }
        int run = (t > 0) ? sh[t - 1] : 0;
        for (int i = 0; i < SCH; i++) {
            int idx = base + i;
            if (idx < NN) {
                off[idx] = run;
                cur[idx] = run;
                run += cnt[idx];
            }
        }
        __syncthreads();
    }
}

// fill with FIELD RESOLUTION: bucket arrays hold the final values, not edge ids
__global__ __launch_bounds__(256) void k_fill(const int* __restrict__ src,
                                              const int* __restrict__ dst,
                                              const int* __restrict__ snid,
                                              const int* __restrict__ dnid,
                                              const float* __restrict__ ew) {
    int e = blockIdx.x * blockDim.x + threadIdx.x;
    if (e < NE) {
        int s = src[e], d = dst[e];
        int ps = atomicAdd(&g_cur_src[s], 1);
        g_nbr_src[ps] = snid[e];
        int pd = atomicAdd(&g_cur_dst[d], 1);
        g_nbr_dst[pd] = dnid[e];
        g_hsrc[pd] = s;
        g_nrm[pd] = -g_deg[s] * ew[e] * g_deg[d];
    }
}

// ---------------- fp32 -> bf16 hi/lo split ----------------
__device__ __forceinline__ void split4(float4 v, uint2& hi, uint2& lo) {
    __nv_bfloat16 h[4], l[4];
    float f[4] = {v.x, v.y, v.z, v.w};
#pragma unroll
    for (int t = 0; t < 4; t++) {
        h[t] = __float2bfloat16(f[t]);
        l[t] = __float2bfloat16(f[t] - __bfloat162float(h[t]));
    }
    hi = *reinterpret_cast<uint2*>(h);
    lo = *reinterpret_cast<uint2*>(l);
}

// ---------------- gather + pack A: per node, no FP atomics, no eid indirection ----
// 4 nodes per 256-thread block; 64 threads per node; thread t owns float4 #t of the row.
__global__ __launch_bounds__(256) void k_gatherA(
    const float* __restrict__ x, const float* __restrict__ h)
{
    int node = blockIdx.x * 4 + (threadIdx.x >> 6);
    int t = threadIdx.x & 63;
    if (node >= NN) return;

    const float4* x4 = reinterpret_cast<const float4*>(x);
    const float4* h4 = reinterpret_cast<const float4*>(h);

    float4 ax = x4[(size_t)node * 64 + t];
    float4 at = make_float4(0.f, 0.f, 0.f, 0.f);

    {
        int o = g_off_src[node], c = g_cnt_src[node];
#pragma unroll 4
        for (int i = 0; i < c; i++) {
            int sn = g_nbr_src[o + i];                 // sequential
            float4 v = x4[(size_t)sn * 64 + t];        // 1-deep chain
            ax.x += v.x; ax.y += v.y; ax.z += v.z; ax.w += v.w;
        }
    }
    {
        int o = g_off_dst[node], c = g_cnt_dst[node];
#pragma unroll 4
        for (int i = 0; i < c; i++) {
            int dn = g_nbr_dst[o + i];                 // sequential
            int s  = g_hsrc[o + i];                    // sequential
            float nm = g_nrm[o + i];                   // sequential
            float4 v = x4[(size_t)dn * 64 + t];
            ax.x += v.x; ax.y += v.y; ax.z += v.z; ax.w += v.w;
            float4 hv = h4[(size_t)s * 64 + t];
            at.x += nm * hv.x; at.y += nm * hv.y; at.z += nm * hv.z; at.w += nm * hv.w;
        }
    }

    float4 hr = h4[(size_t)node * 64 + t];

    uint2 hi, lo;
    size_t rb = (size_t)node * KTOT;
    split4(ax, hi, lo);
    *reinterpret_cast<uint2*>(g_Ah + rb + t * 4) = hi;
    *reinterpret_cast<uint2*>(g_Al + rb + t * 4) = lo;
    split4(hr, hi, lo);
    *reinterpret_cast<uint2*>(g_Ah + rb + 256 + t * 4) = hi;
    *reinterpret_cast<uint2*>(g_Al + rb + 256 + t * 4) = lo;
    split4(at, hi, lo);
    *reinterpret_cast<uint2*>(g_Ah + rb + 512 + t * 4) = hi;
    *reinterpret_cast<uint2*>(g_Al + rb + 512 + t * 4) = lo;
}

// ---------------- weight packs ----------------
__device__ __forceinline__ void split8(const float* v, uint4& hi4, uint4& lo4) {
    __nv_bfloat16 h[8], l[8];
#pragma unroll
    for (int t = 0; t < 8; t++) {
        h[t] = __float2bfloat16(v[t]);
        l[t] = __float2bfloat16(v[t] - __bfloat162float(h[t]));
    }
    hi4 = *reinterpret_cast<uint4*>(h);
    lo4 = *reinterpret_cast<uint4*>(l);
}

__global__ __launch_bounds__(256) void k_conv_W(
    const float* __restrict__ Wi, const float* __restrict__ Wf,
    const float* __restrict__ Wg, const float* __restrict__ Wo,
    const float* __restrict__ Wci, const float* __restrict__ Wcf,
    const float* __restrict__ Wcg, const float* __restrict__ Wco)
{
    int i = blockIdx.x * blockDim.x + threadIdx.x;   // over NCOL*96
    if (i >= NCOL * 96) return;
    int n = i / 96;
    int kc = i % 96;
    int g = n >> 8, j = n & 255;
    const float* Win[4] = {Wi, Wf, Wg, Wo};
    const float* Wc[4]  = {Wci, Wcf, Wcg, Wco};
    float v[8];
#pragma unroll
    for (int t = 0; t < 8; t++) {
        int k = kc * 8 + t;
        if (k < 256)      v[t] = Win[g][k * 256 + j];
        else if (k < 512) v[t] = Wc[g][(k - 256) * 256 + j];
        else              v[t] = Wc[g][65536 + (k - 512) * 256 + j];
    }
    uint4 hi4, lo4;
    split8(v, hi4, lo4);
    reinterpret_cast<uint4*>(g_Wh)[i] = hi4;
    reinterpret_cast<uint4*>(g_Wl)[i] = lo4;
}

__global__ __launch_bounds__(256) void k_conv_Wlin(const float* __restrict__ Wlin) {
    int i = blockIdx.x * blockDim.x + threadIdx.x;   // over 256*32
    if (i >= HD * 32) return;
    int n = i / 32;
    int kc = i % 32;
    float v[8];
#pragma unroll
    for (int t = 0; t < 8; t++) v[t] = Wlin[(kc * 8 + t) * 256 + n];
    uint4 hi4, lo4;
    split8(v, hi4, lo4);
    reinterpret_cast<uint4*>(g_WlTh)[i] = hi4;
    reinterpret_cast<uint4*>(g_WlTl)[i] = lo4;
}

// ============ bf16-split GEMM via mma.sync (exact R3 config: NSTG=3) ============
#define BKG   32
#define NSTG  3
#define TSTR  80
#define TILEB (128 * TSTR)
#define STAGEB (4 * TILEB)
#define SMEM_GEMM (NSTG * STAGEB)

__device__ __forceinline__ void cp16(uint32_t saddr, const void* gaddr) {
    asm volatile("cp.async.cg.shared.global [%0], [%1], 16;" :: "r"(saddr), "l"(gaddr));
}
__device__ __forceinline__ void ldm_x4(uint32_t* r, uint32_t a) {
    asm volatile("ldmatrix.sync.aligned.m8n8.x4.shared.b16 {%0,%1,%2,%3}, [%4];"
                 : "=r"(r[0]), "=r"(r[1]), "=r"(r[2]), "=r"(r[3]) : "r"(a));
}
__device__ __forceinline__ void ldm_x2(uint32_t* r, uint32_t a) {
    asm volatile("ldmatrix.sync.aligned.m8n8.x2.shared.b16 {%0,%1}, [%2];"
                 : "=r"(r[0]), "=r"(r[1]) : "r"(a));
}
__device__ __forceinline__ void mma16816(float* c, const uint32_t* a, const uint32_t* b) {
    asm volatile(
        "mma.sync.aligned.m16n8k16.row.col.f32.bf16.bf16.f32 "
        "{%0,%1,%2,%3}, {%4,%5,%6,%7}, {%8,%9}, {%0,%1,%2,%3};"
        : "+f"(c[0]), "+f"(c[1]), "+f"(c[2]), "+f"(c[3])
        : "r"(a[0]), "r"(a[1]), "r"(a[2]), "r"(a[3]), "r"(b[0]), "r"(b[1]));
}

__global__ __launch_bounds__(256) void k_mma(
    const __nv_bfloat16* __restrict__ Ah, const __nv_bfloat16* __restrict__ Al,
    const __nv_bfloat16* __restrict__ Bh, const __nv_bfloat16* __restrict__ Bl,
    float* __restrict__ C, int K, int Ncols, const float* __restrict__ bias, int m_limit)
{
    extern __shared__ char smem[];
    const int tid = threadIdx.x;
    const int wid = tid >> 5;
    const int lane = tid & 31;
    const int m0 = blockIdx.y * 128;
    const int n0 = blockIdx.x * 128;
    const int nkt = K / BKG;
    const uint32_t sb = smem_u32(smem);

    const int wr = (wid >> 2) * 64;
    const int wc = (wid & 3) * 32;

    const int r0c = tid >> 2, c0c = tid & 3;
    const int r1c = (tid + 256) >> 2, c1c = tid & 3;

    float acc[4][4][4] = {};

    auto issue_stage = [&](int kt, int buf) {
        uint32_t s = sb + buf * STAGEB;
        const char* ahB = reinterpret_cast<const char*>(Ah);
        const char* alB = reinterpret_cast<const char*>(Al);
        const char* bhB = reinterpret_cast<const char*>(Bh);
        const char* blB = reinterpret_cast<const char*>(Bl);
        size_t kb = (size_t)kt * BKG * 2;
        {
            size_t ga = ((size_t)(m0 + r0c) * K) * 2 + kb + c0c * 16;
            size_t gb = ((size_t)(n0 + r0c) * K) * 2 + kb + c0c * 16;
            uint32_t so = r0c * TSTR + c0c * 16;
            cp16(s + so, ahB + ga);
            cp16(s + TILEB + so, alB + ga);
            cp16(s + 2 * TILEB + so, bhB + gb);
            cp16(s + 3 * TILEB + so, blB + gb);
        }
        {
            size_t ga = ((size_t)(m0 + r1c) * K) * 2 + kb + c1c * 16;
            size_t gb = ((size_t)(n0 + r1c) * K) * 2 + kb + c1c * 16;
            uint32_t so = r1c * TSTR + c1c * 16;
            cp16(s + so, ahB + ga);
            cp16(s + TILEB + so, alB + ga);
            cp16(s + 2 * TILEB + so, bhB + gb);
            cp16(s + 3 * TILEB + so, blB + gb);
        }
    };

    for (int s = 0; s < NSTG - 1; s++) {
        if (s < nkt) issue_stage(s, s);
        asm volatile("cp.async.commit_group;");
    }

    for (int kt = 0; kt < nkt; kt++) {
        asm volatile("cp.async.wait_group %0;" :: "n"(NSTG - 2));
        __syncthreads();

        uint32_t s = sb + (kt % NSTG) * STAGEB;
        uint32_t sAh = s, sAl = s + TILEB, sBh = s + 2 * TILEB, sBl = s + 3 * TILEB;

#pragma unroll
        for (int ks = 0; ks < 2; ks++) {
            uint32_t ah[4][4], al[4][4], bh[4][2], bl[4][2];
            uint32_t aoff = (wr + (lane & 15)) * TSTR + ks * 32 + ((lane >> 4) & 1) * 16;
#pragma unroll
            for (int mt = 0; mt < 4; mt++) {
                ldm_x4(ah[mt], sAh + aoff + mt * 16 * TSTR);
                ldm_x4(al[mt], sAl + aoff + mt * 16 * TSTR);
            }
            int l = lane & 15;
            uint32_t boff = (wc + (l & 7)) * TSTR + ks * 32 + ((l >> 3) & 1) * 16;
#pragma unroll
            for (int nt = 0; nt < 4; nt++) {
                ldm_x2(bh[nt], sBh + boff + nt * 8 * TSTR);
                ldm_x2(bl[nt], sBl + boff + nt * 8 * TSTR);
            }
#pragma unroll
            for (int mt = 0; mt < 4; mt++)
#pragma unroll
                for (int nt = 0; nt < 4; nt++) {
                    mma16816(acc[mt][nt], ah[mt], bh[nt]);
                    mma16816(acc[mt][nt], ah[mt], bl[nt]);
                    mma16816(acc[mt][nt], al[mt], bh[nt]);
                }
        }
        __syncthreads();
        int nk = kt + NSTG - 1;
        if (nk < nkt) issue_stage(nk, nk % NSTG);
        asm volatile("cp.async.commit_group;");
    }

#pragma unroll
    for (int mt = 0; mt < 4; mt++) {
        int rA = m0 + wr + mt * 16 + (lane >> 2);
        int rB = rA + 8;
#pragma unroll
        for (int nt = 0; nt < 4; nt++) {
            int col = n0 + wc + nt * 8 + (lane & 3) * 2;
            float bx = 0.f, by = 0.f;
            if (bias) { bx = bias[col]; by = bias[col + 1]; }
            if (rA < m_limit) {
                float2 v = make_float2(acc[mt][nt][0] + bx, acc[mt][nt][1] + by);
                *reinterpret_cast<float2*>(C + (size_t)rA * Ncols + col) = v;
            }
            if (rB < m_limit) {
                float2 v = make_float2(acc[mt][nt][2] + bx, acc[mt][nt][3] + by);
                *reinterpret_cast<float2*>(C + (size_t)rB * Ncols + col) = v;
            }
        }
    }
}

// ---------------- gates: h0, c_new, relu split ----------------
__global__ __launch_bounds__(256) void k_gates(
    const float* __restrict__ c,
    const float* __restrict__ bci, const float* __restrict__ bcf,
    const float* __restrict__ bcg, const float* __restrict__ bco,
    const float* __restrict__ bi, const float* __restrict__ bf,
    const float* __restrict__ bg, const float* __restrict__ bo,
    const float* __restrict__ wci, const float* __restrict__ wcf,
    const float* __restrict__ wco,
    float* __restrict__ out)
{
    int idx = blockIdx.x * blockDim.x + threadIdx.x;
    if (idx >= MPAD * HD) return;
    int row = idx >> 8;
    int j = idx & 255;
    if (row >= NN) {
        g_Rh[idx] = __float2bfloat16(0.f);
        g_Rl[idx] = __float2bfloat16(0.f);
        return;
    }
    const float* z = g_Z + (size_t)row * NCOL;
    float cv = c[idx];
    float ig = sigf(z[j]       + bci[j] + bi[j] + wci[j] * cv);
    float fg = sigf(z[256 + j] + bcf[j] + bf[j] + wcf[j] * cv);
    float gg = tanhf(z[512 + j] + bcg[j] + bg[j]);
    float cn = fg * cv + ig * gg;
    float og = sigf(z[768 + j] + bco[j] + bo[j] + wco[j] * cn);
    float h0 = og * tanhf(cn);
    out[NH + idx]     = h0;
    out[2 * NH + idx] = cn;
    float r = fmaxf(h0, 0.f);
    __nv_bfloat16 rh = __float2bfloat16(r);
    __nv_bfloat16 rl = __float2bfloat16(r - __bfloat162float(rh));
    g_Rh[idx] = rh;
    g_Rl[idx] = rl;
}

// ---------------- launch ----------------
extern "C" void kernel_launch(void* const* d_in, const int* in_sizes, int n_in,
                              void* d_out, int out_size) {
    const float* x    = (const float*)d_in[0];
    const int*   ei   = (const int*)d_in[1];
    const float* ew   = (const float*)d_in[2];
    const float* h    = (const float*)d_in[3];
    const float* c    = (const float*)d_in[4];
    const int*   snid = (const int*)d_in[5];
    const int*   dnid = (const int*)d_in[6];
    const float* Wi   = (const float*)d_in[7];
    const float* Wf   = (const float*)d_in[8];
    const float* Wg   = (const float*)d_in[9];
    const float* Wo   = (const float*)d_in[10];
    const float* Wci  = (const float*)d_in[11];
    const float* Wcf  = (const float*)d_in[12];
    const float* Wcg  = (const float*)d_in[13];
    const float* Wco  = (const float*)d_in[14];
    const float* bci  = (const float*)d_in[15];
    const float* bcf  = (const float*)d_in[16];
    const float* bcg  = (const float*)d_in[17];
    const float* bco  = (const float*)d_in[18];

    const float *bi, *bf, *bg, *bo, *blin, *wci, *wcf, *wco, *Wlin;
    if (in_sizes[27] == 65536) {
        bi = (const float*)d_in[19]; bf = (const float*)d_in[20];
        bg = (const float*)d_in[21]; bo = (const float*)d_in[22];
        blin = (const float*)d_in[23];
        wci = (const float*)d_in[24]; wcf = (const float*)d_in[25];
        wco = (const float*)d_in[26];
        Wlin = (const float*)d_in[27];
    } else {
        wci = (const float*)d_in[19]; wcf = (const float*)d_in[20];
        wco = (const float*)d_in[21];
        bi = (const float*)d_in[22]; bf = (const float*)d_in[23];
        bg = (const float*)d_in[24]; bo = (const float*)d_in[25];
        Wlin = (const float*)d_in[26];
        blin = (const float*)d_in[27];
    }

    const int* src = ei;
    const int* dst = ei + NE;
    float* out = (float*)d_out;

    cudaFuncSetAttribute(k_mma, cudaFuncAttributeMaxDynamicSharedMemorySize, SMEM_GEMM);

    // CSR build (field-resolving) + weight packs
    k_zero<<<(NN + 255) / 256, 256>>>();
    k_conv_W<<<(NCOL * 96 + 255) / 256, 256>>>(Wi, Wf, Wg, Wo, Wci, Wcf, Wcg, Wco);
    k_conv_Wlin<<<(HD * 32 + 255) / 256, 256>>>(Wlin);
    k_count<<<(NE + 255) / 256, 256>>>(src, dst, ew);
    k_dinv<<<(NN + 255) / 256, 256>>>();
    k_scan<<<1, 1024>>>();
    k_fill<<<(NE + 255) / 256, 256>>>(src, dst, snid, dnid, ew);

    // gather + pack A directly (no scatters, no eid indirection)
    k_gatherA<<<(NN + 3) / 4, 256>>>(x, h);

    float *Ah, *Al, *Wh, *Wl, *Zp, *Rh, *Rl, *WlTh, *WlTl;
    cudaGetSymbolAddress((void**)&Ah, g_Ah);
    cudaGetSymbolAddress((void**)&Al, g_Al);
    cudaGetSymbolAddress((void**)&Wh, g_Wh);
    cudaGetSymbolAddress((void**)&Wl, g_Wl);
    cudaGetSymbolAddress((void**)&Zp, g_Z);
    cudaGetSymbolAddress((void**)&Rh, g_Rh);
    cudaGetSymbolAddress((void**)&Rl, g_Rl);
    cudaGetSymbolAddress((void**)&WlTh, g_WlTh);
    cudaGetSymbolAddress((void**)&WlTl, g_WlTl);

    // big GEMM: Z[MPAD x 1024] = A @ W^T
    {
        dim3 grid(NCOL / 128, MPAD / 128);
        k_mma<<<grid, 256, SMEM_GEMM>>>(
            (const __nv_bfloat16*)Ah, (const __nv_bfloat16*)Al,
            (const __nv_bfloat16*)Wh, (const __nv_bfloat16*)Wl,
            Zp, KTOT, NCOL, nullptr, MPAD);
    }

    k_gates<<<(MPAD * HD + 255) / 256, 256>>>(c, bci, bcf, bcg, bco, bi, bf, bg, bo,
                                              wci, wcf, wco, out);

    // small GEMM: h_out[NN x 256] = relu(h0) @ W_lin + b_lin
    {
        dim3 grid(HD / 128, MPAD / 128);
        k_mma<<<grid, 256, SMEM_GEMM>>>(
            (const __nv_bfloat16*)Rh, (const __nv_bfloat16*)Rl,
            (const __nv_bfloat16*)WlTh, (const __nv_bfloat16*)WlTl,
            out, HD, HD, blin, NN);
    }
}

// round 10
// speedup vs baseline: 1.7674x; 1.1663x over previous
#include <cuda_runtime.h>
#include <cuda_fp16.h>
#include <math.h>
#include <stdint.h>

// Problem constants
#define NN    30000
#define NE    480000
#define HD    256
#define MPAD  30080      // 235*128
#define KTOT  768        // x_aug | h | t1
#define NCOL  1024       // 4 gates * 256 (gate-blocked: col = g*256 + j)
#define NH    (NN * HD)

// ---------------- static device scratch ----------------
__device__ float g_deg[NN];
__device__ int   g_cnt_src[NN], g_cnt_dst[NN];
__device__ int   g_off_src[NN], g_off_dst[NN];
__device__ int   g_cur_src[NN], g_cur_dst[NN];
__device__ int   g_nbr_src[NE];                   // resolved: snid[e] bucketed by src
__device__ int   g_nbr_dst[NE];                   // resolved: dnid[e] bucketed by dst
__device__ int   g_hsrc[NE];                      // resolved: src[e]  bucketed by dst
__device__ float g_nrm[NE];                       // resolved: norm_e  bucketed by dst
__device__ float g_Z[MPAD * NCOL];                // gate pre-activations (fp32)
__device__ __align__(16) __half g_Ah[MPAD * KTOT];   // A hi (fp16); pad rows stay 0
__device__ __align__(16) __half g_Al[MPAD * KTOT];   // A lo (fp16)
__device__ __align__(16) __half g_W [NCOL * KTOT];   // W transposed [n][k], single fp16
__device__ __align__(16) __half g_Rh[MPAD * HD];     // relu(h0) hi
__device__ __align__(16) __half g_Rl[MPAD * HD];     // relu(h0) lo
__device__ __align__(16) __half g_WlT[HD * HD];      // W_lin transposed, single fp16

__device__ __forceinline__ float sigf(float x) { return 1.0f / (1.0f + __expf(-x)); }
__device__ __forceinline__ float tanhfast(float x) {
    return 2.0f / (1.0f + __expf(-2.0f * x)) - 1.0f;
}

__device__ __forceinline__ uint32_t smem_u32(const void* p) {
    uint32_t a;
    asm("{ .reg .u64 t; cvta.to.shared.u64 t, %1; cvt.u32.u64 %0, t; }" : "=r"(a) : "l"(p));
    return a;
}

// ---------------- CSR build ----------------
__global__ __launch_bounds__(256) void k_zero() {
    int i = blockIdx.x * blockDim.x + threadIdx.x;
    if (i < NN) { g_cnt_src[i] = 0; g_cnt_dst[i] = 0; g_deg[i] = 0.f; }
}

__global__ __launch_bounds__(256) void k_count(const int* __restrict__ src,
                                               const int* __restrict__ dst,
                                               const float* __restrict__ ew) {
    int e = blockIdx.x * blockDim.x + threadIdx.x;
    if (e < NE) {
        int s = src[e], d = dst[e];
        atomicAdd(&g_cnt_src[s], 1);
        atomicAdd(&g_cnt_dst[d], 1);
        atomicAdd(&g_deg[s], ew[e]);
    }
}

__global__ __launch_bounds__(256) void k_dinv() {
    int i = blockIdx.x * blockDim.x + threadIdx.x;
    if (i < NN) {
        float d = g_deg[i];
        g_deg[i] = (d > 0.f) ? rsqrtf(fmaxf(d, 1e-12f)) : 0.f;
    }
}

#define SCH 30   // 1024*30 = 30720 >= NN
__global__ __launch_bounds__(1024) void k_scan() {
    __shared__ int sh[1024];
    int t = threadIdx.x;
    int base = t * SCH;
#pragma unroll 1
    for (int pass = 0; pass < 2; pass++) {
        const int* cnt = pass ? g_cnt_dst : g_cnt_src;
        int* off = pass ? g_off_dst : g_off_src;
        int* cur = pass ? g_cur_dst : g_cur_src;
        int local = 0;
        for (int i = 0; i < SCH; i++) {
            int idx = base + i;
            if (idx < NN) local += cnt[idx];
        }
        sh[t] = local;
        __syncthreads();
        for (int o = 1; o < 1024; o <<= 1) {
            int v = 0;
            if (t >= o) v = sh[t - o];
            __syncthreads();
            if (t >= o) sh[t] += v;
            __syncthreads();
        }
        int run = (t > 0) ? sh[t - 1] : 0;
        for (int i = 0; i < SCH; i++) {
            int idx = base + i;
            if (idx < NN) {
                off[idx] = run;
                cur[idx] = run;
                run += cnt[idx];
            }
        }
        __syncthreads();
    }
}

__global__ __launch_bounds__(256) void k_fill(const int* __restrict__ src,
                                              const int* __restrict__ dst,
                                              const int* __restrict__ snid,
                                              const int* __restrict__ dnid,
                                              const float* __restrict__ ew) {
    int e = blockIdx.x * blockDim.x + threadIdx.x;
    if (e < NE) {
        int s = src[e], d = dst[e];
        int ps = atomicAdd(&g_cur_src[s], 1);
        g_nbr_src[ps] = snid[e];
        int pd = atomicAdd(&g_cur_dst[d], 1);
        g_nbr_dst[pd] = dnid[e];
        g_hsrc[pd] = s;
        g_nrm[pd] = -g_deg[s] * ew[e] * g_deg[d];
    }
}

// ---------------- fp32 -> fp16 hi/lo split ----------------
__device__ __forceinline__ void split4h(float4 v, uint2& hi, uint2& lo) {
    __half h[4], l[4];
    float f[4] = {v.x, v.y, v.z, v.w};
#pragma unroll
    for (int t = 0; t < 4; t++) {
        h[t] = __float2half(f[t]);
        l[t] = __float2half(f[t] - __half2float(h[t]));
    }
    hi = *reinterpret_cast<uint2*>(h);
    lo = *reinterpret_cast<uint2*>(l);
}

// ---------------- gather + pack A (fp16 split), no FP atomics, no eid indirection ----
__global__ __launch_bounds__(256) void k_gatherA(
    const float* __restrict__ x, const float* __restrict__ h)
{
    int node = blockIdx.x * 4 + (threadIdx.x >> 6);
    int t = threadIdx.x & 63;
    if (node >= NN) return;

    const float4* x4 = reinterpret_cast<const float4*>(x);
    const float4* h4 = reinterpret_cast<const float4*>(h);

    float4 ax = x4[(size_t)node * 64 + t];
    float4 at = make_float4(0.f, 0.f, 0.f, 0.f);

    {
        int o = g_off_src[node], c = g_cnt_src[node];
#pragma unroll 4
        for (int i = 0; i < c; i++) {
            int sn = g_nbr_src[o + i];
            float4 v = x4[(size_t)sn * 64 + t];
            ax.x += v.x; ax.y += v.y; ax.z += v.z; ax.w += v.w;
        }
    }
    {
        int o = g_off_dst[node], c = g_cnt_dst[node];
#pragma unroll 4
        for (int i = 0; i < c; i++) {
            int dn = g_nbr_dst[o + i];
            int s  = g_hsrc[o + i];
            float nm = g_nrm[o + i];
            float4 v = x4[(size_t)dn * 64 + t];
            ax.x += v.x; ax.y += v.y; ax.z += v.z; ax.w += v.w;
            float4 hv = h4[(size_t)s * 64 + t];
            at.x += nm * hv.x; at.y += nm * hv.y; at.z += nm * hv.z; at.w += nm * hv.w;
        }
    }

    float4 hr = h4[(size_t)node * 64 + t];

    uint2 hi, lo;
    size_t rb = (size_t)node * KTOT;
    split4h(ax, hi, lo);
    *reinterpret_cast<uint2*>(g_Ah + rb + t * 4) = hi;
    *reinterpret_cast<uint2*>(g_Al + rb + t * 4) = lo;
    split4h(hr, hi, lo);
    *reinterpret_cast<uint2*>(g_Ah + rb + 256 + t * 4) = hi;
    *reinterpret_cast<uint2*>(g_Al + rb + 256 + t * 4) = lo;
    split4h(at, hi, lo);
    *reinterpret_cast<uint2*>(g_Ah + rb + 512 + t * 4) = hi;
    *reinterpret_cast<uint2*>(g_Al + rb + 512 + t * 4) = lo;
}

// ---------------- weight packs (single fp16) ----------------
__global__ __launch_bounds__(256) void k_conv_W(
    const float* __restrict__ Wi, const float* __restrict__ Wf,
    const float* __restrict__ Wg, const float* __restrict__ Wo,
    const float* __restrict__ Wci, const float* __restrict__ Wcf,
    const float* __restrict__ Wcg, const float* __restrict__ Wco)
{
    int i = blockIdx.x * blockDim.x + threadIdx.x;   // over NCOL*96
    if (i >= NCOL * 96) return;
    int n = i / 96;
    int kc = i % 96;
    int g = n >> 8, j = n & 255;
    const float* Win[4] = {Wi, Wf, Wg, Wo};
    const float* Wc[4]  = {Wci, Wcf, Wcg, Wco};
    __half v[8];
#pragma unroll
    for (int t = 0; t < 8; t++) {
        int k = kc * 8 + t;
        float f;
        if (k < 256)      f = Win[g][k * 256 + j];
        else if (k < 512) f = Wc[g][(k - 256) * 256 + j];
        else              f = Wc[g][65536 + (k - 512) * 256 + j];
        v[t] = __float2half(f);
    }
    reinterpret_cast<uint4*>(g_W)[i] = *reinterpret_cast<uint4*>(v);
}

__global__ __launch_bounds__(256) void k_conv_Wlin(const float* __restrict__ Wlin) {
    int i = blockIdx.x * blockDim.x + threadIdx.x;   // over 256*32
    if (i >= HD * 32) return;
    int n = i / 32;
    int kc = i % 32;
    __half v[8];
#pragma unroll
    for (int t = 0; t < 8; t++) v[t] = __float2half(Wlin[(kc * 8 + t) * 256 + n]);
    reinterpret_cast<uint4*>(g_WlT)[i] = *reinterpret_cast<uint4*>(v);
}

// ============ fp16 2-product GEMM via mma.sync ============
// C = (Ah + Al)[M x K] @ B^T, B stored [Ncols x K] row-major fp16.
// CTA tile 128x128x32, 3-stage cp.async pipeline, 8 warps (2x4), warp tile 64x32.
#define BKG   32
#define NSTG  3
#define TSTR  80
#define TILEB (128 * TSTR)
#define STAGEB (3 * TILEB)         // Ah, Al, B
#define SMEM_GEMM (NSTG * STAGEB)  // 92160 B

__device__ __forceinline__ void cp16(uint32_t saddr, const void* gaddr) {
    asm volatile("cp.async.cg.shared.global [%0], [%1], 16;" :: "r"(saddr), "l"(gaddr));
}
__device__ __forceinline__ void ldm_x4(uint32_t* r, uint32_t a) {
    asm volatile("ldmatrix.sync.aligned.m8n8.x4.shared.b16 {%0,%1,%2,%3}, [%4];"
                 : "=r"(r[0]), "=r"(r[1]), "=r"(r[2]), "=r"(r[3]) : "r"(a));
}
__device__ __forceinline__ void ldm_x2(uint32_t* r, uint32_t a) {
    asm volatile("ldmatrix.sync.aligned.m8n8.x2.shared.b16 {%0,%1}, [%2];"
                 : "=r"(r[0]), "=r"(r[1]) : "r"(a));
}
__device__ __forceinline__ void mma16816h(float* c, const uint32_t* a, const uint32_t* b) {
    asm volatile(
        "mma.sync.aligned.m16n8k16.row.col.f32.f16.f16.f32 "
        "{%0,%1,%2,%3}, {%4,%5,%6,%7}, {%8,%9}, {%0,%1,%2,%3};"
        : "+f"(c[0]), "+f"(c[1]), "+f"(c[2]), "+f"(c[3])
        : "r"(a[0]), "r"(a[1]), "r"(a[2]), "r"(a[3]), "r"(b[0]), "r"(b[1]));
}

__global__ __launch_bounds__(256) void k_mma(
    const __half* __restrict__ Ah, const __half* __restrict__ Al,
    const __half* __restrict__ B,
    float* __restrict__ C, int K, int Ncols, const float* __restrict__ bias, int m_limit)
{
    extern __shared__ char smem[];
    const int tid = threadIdx.x;
    const int wid = tid >> 5;
    const int lane = tid & 31;
    const int m0 = blockIdx.y * 128;
    const int n0 = blockIdx.x * 128;
    const int nkt = K / BKG;
    const uint32_t sb = smem_u32(smem);

    const int wr = (wid >> 2) * 64;
    const int wc = (wid & 3) * 32;

    const int r0c = tid >> 2, c0c = tid & 3;
    const int r1c = (tid + 256) >> 2, c1c = tid & 3;

    float acc[4][4][4] = {};

    auto issue_stage = [&](int kt, int buf) {
        uint32_t s = sb + buf * STAGEB;
        const char* ahB = reinterpret_cast<const char*>(Ah);
        const char* alB = reinterpret_cast<const char*>(Al);
        const char* bB  = reinterpret_cast<const char*>(B);
        size_t kb = (size_t)kt * BKG * 2;
        {
            size_t ga = ((size_t)(m0 + r0c) * K) * 2 + kb + c0c * 16;
            size_t gb = ((size_t)(n0 + r0c) * K) * 2 + kb + c0c * 16;
            uint32_t so = r0c * TSTR + c0c * 16;
            cp16(s + so, ahB + ga);
            cp16(s + TILEB + so, alB + ga);
            cp16(s + 2 * TILEB + so, bB + gb);
        }
        {
            size_t ga = ((size_t)(m0 + r1c) * K) * 2 + kb + c1c * 16;
            size_t gb = ((size_t)(n0 + r1c) * K) * 2 + kb + c1c * 16;
            uint32_t so = r1c * TSTR + c1c * 16;
            cp16(s + so, ahB + ga);
            cp16(s + TILEB + so, alB + ga);
            cp16(s + 2 * TILEB + so, bB + gb);
        }
    };

    for (int s = 0; s < NSTG - 1; s++) {
        if (s < nkt) issue_stage(s, s);
        asm volatile("cp.async.commit_group;");
    }

    for (int kt = 0; kt < nkt; kt++) {
        asm volatile("cp.async.wait_group %0;" :: "n"(NSTG - 2));
        __syncthreads();

        uint32_t s = sb + (kt % NSTG) * STAGEB;
        uint32_t sAh = s, sAl = s + TILEB, sB = s + 2 * TILEB;

#pragma unroll
        for (int ks = 0; ks < 2; ks++) {
            uint32_t ah[4][4], al[4][4], bh[4][2];
            uint32_t aoff = (wr + (lane & 15)) * TSTR + ks * 32 + ((lane >> 4) & 1) * 16;
#pragma unroll
            for (int mt = 0; mt < 4; mt++) {
                ldm_x4(ah[mt], sAh + aoff + mt * 16 * TSTR);
                ldm_x4(al[mt], sAl + aoff + mt * 16 * TSTR);
            }
            int l = lane & 15;
            uint32_t boff = (wc + (l & 7)) * TSTR + ks * 32 + ((l >> 3) & 1) * 16;
#pragma unroll
            for (int nt = 0; nt < 4; nt++) {
                ldm_x2(bh[nt], sB + boff + nt * 8 * TSTR);
            }
#pragma unroll
            for (int mt = 0; mt < 4; mt++)
#pragma unroll
                for (int nt = 0; nt < 4; nt++) {
                    mma16816h(acc[mt][nt], ah[mt], bh[nt]);
                    mma16816h(acc[mt][nt], al[mt], bh[nt]);
                }
        }
        __syncthreads();
        int nk = kt + NSTG - 1;
        if (nk < nkt) issue_stage(nk, nk % NSTG);
        asm volatile("cp.async.commit_group;");
    }

#pragma unroll
    for (int mt = 0; mt < 4; mt++) {
        int rA = m0 + wr + mt * 16 + (lane >> 2);
        int rB = rA + 8;
#pragma unroll
        for (int nt = 0; nt < 4; nt++) {
            int col = n0 + wc + nt * 8 + (lane & 3) * 2;
            float bx = 0.f, by = 0.f;
            if (bias) { bx = bias[col]; by = bias[col + 1]; }
            if (rA < m_limit) {
                float2 v = make_float2(acc[mt][nt][0] + bx, acc[mt][nt][1] + by);
                *reinterpret_cast<float2*>(C + (size_t)rA * Ncols + col) = v;
            }
            if (rB < m_limit) {
                float2 v = make_float2(acc[mt][nt][2] + bx, acc[mt][nt][3] + by);
                *reinterpret_cast<float2*>(C + (size_t)rB * Ncols + col) = v;
            }
        }
    }
}

// ---------------- gates: h0, c_new, relu split (fp16) ----------------
__global__ __launch_bounds__(256) void k_gates(
    const float* __restrict__ c,
    const float* __restrict__ bci, const float* __restrict__ bcf,
    const float* __restrict__ bcg, const float* __restrict__ bco,
    const float* __restrict__ bi, const float* __restrict__ bf,
    const float* __restrict__ bg, const float* __restrict__ bo,
    const float* __restrict__ wci, const float* __restrict__ wcf,
    const float* __restrict__ wco,
    float* __restrict__ out)
{
    int idx = blockIdx.x * blockDim.x + threadIdx.x;
    if (idx >= MPAD * HD) return;
    int row = idx >> 8;
    int j = idx & 255;
    if (row >= NN) {
        g_Rh[idx] = __float2half(0.f);
        g_Rl[idx] = __float2half(0.f);
        return;
    }
    const float* z = g_Z + (size_t)row * NCOL;
    float cv = c[idx];
    float ig = sigf(z[j]       + bci[j] + bi[j] + wci[j] * cv);
    float fg = sigf(z[256 + j] + bcf[j] + bf[j] + wcf[j] * cv);
    float gg = tanhfast(z[512 + j] + bcg[j] + bg[j]);
    float cn = fg * cv + ig * gg;
    float og = sigf(z[768 + j] + bco[j] + bo[j] + wco[j] * cn);
    float h0 = og * tanhfast(cn);
    out[NH + idx]     = h0;
    out[2 * NH + idx] = cn;
    float r = fmaxf(h0, 0.f);
    __half rh = __float2half(r);
    __half rl = __float2half(r - __half2float(rh));
    g_Rh[idx] = rh;
    g_Rl[idx] = rl;
}

// ---------------- launch ----------------
extern "C" void kernel_launch(void* const* d_in, const int* in_sizes, int n_in,
                              void* d_out, int out_size) {
    const float* x    = (const float*)d_in[0];
    const int*   ei   = (const int*)d_in[1];
    const float* ew   = (const float*)d_in[2];
    const float* h    = (const float*)d_in[3];
    const float* c    = (const float*)d_in[4];
    const int*   snid = (const int*)d_in[5];
    const int*   dnid = (const int*)d_in[6];
    const float* Wi   = (const float*)d_in[7];
    const float* Wf   = (const float*)d_in[8];
    const float* Wg   = (const float*)d_in[9];
    const float* Wo   = (const float*)d_in[10];
    const float* Wci  = (const float*)d_in[11];
    const float* Wcf  = (const float*)d_in[12];
    const float* Wcg  = (const float*)d_in[13];
    const float* Wco  = (const float*)d_in[14];
    const float* bci  = (const float*)d_in[15];
    const float* bcf  = (const float*)d_in[16];
    const float* bcg  = (const float*)d_in[17];
    const float* bco  = (const float*)d_in[18];

    const float *bi, *bf, *bg, *bo, *blin, *wci, *wcf, *wco, *Wlin;
    if (in_sizes[27] == 65536) {
        bi = (const float*)d_in[19]; bf = (const float*)d_in[20];
        bg = (const float*)d_in[21]; bo = (const float*)d_in[22];
        blin = (const float*)d_in[23];
        wci = (const float*)d_in[24]; wcf = (const float*)d_in[25];
        wco = (const float*)d_in[26];
        Wlin = (const float*)d_in[27];
    } else {
        wci = (const float*)d_in[19]; wcf = (const float*)d_in[20];
        wco = (const float*)d_in[21];
        bi = (const float*)d_in[22]; bf = (const float*)d_in[23];
        bg = (const float*)d_in[24]; bo = (const float*)d_in[25];
        Wlin = (const float*)d_in[26];
        blin = (const float*)d_in[27];
    }

    const int* src = ei;
    const int* dst = ei + NE;
    float* out = (float*)d_out;

    cudaFuncSetAttribute(k_mma, cudaFuncAttributeMaxDynamicSharedMemorySize, SMEM_GEMM);

    // CSR build (field-resolving) + weight packs
    k_zero<<<(NN + 255) / 256, 256>>>();
    k_conv_W<<<(NCOL * 96 + 255) / 256, 256>>>(Wi, Wf, Wg, Wo, Wci, Wcf, Wcg, Wco);
    k_conv_Wlin<<<(HD * 32 + 255) / 256, 256>>>(Wlin);
    k_count<<<(NE + 255) / 256, 256>>>(src, dst, ew);
    k_dinv<<<(NN + 255) / 256, 256>>>();
    k_scan<<<1, 1024>>>();
    k_fill<<<(NE + 255) / 256, 256>>>(src, dst, snid, dnid, ew);

    // gather + pack A directly
    k_gatherA<<<(NN + 3) / 4, 256>>>(x, h);

    __half *Ah, *Al, *Wp, *Rh, *Rl, *WlT;
    float *Zp;
    cudaGetSymbolAddress((void**)&Ah, g_Ah);
    cudaGetSymbolAddress((void**)&Al, g_Al);
    cudaGetSymbolAddress((void**)&Wp, g_W);
    cudaGetSymbolAddress((void**)&Zp, g_Z);
    cudaGetSymbolAddress((void**)&Rh, g_Rh);
    cudaGetSymbolAddress((void**)&Rl, g_Rl);
    cudaGetSymbolAddress((void**)&WlT, g_WlT);

    // big GEMM: Z[MPAD x 1024] = (Ah+Al) @ W^T   (2-product fp16)
    {
        dim3 grid(NCOL / 128, MPAD / 128);
        k_mma<<<grid, 256, SMEM_GEMM>>>(Ah, Al, Wp, Zp, KTOT, NCOL, nullptr, MPAD);
    }

    k_gates<<<(MPAD * HD + 255) / 256, 256>>>(c, bci, bcf, bcg, bco, bi, bf, bg, bo,
                                              wci, wcf, wco, out);

    // small GEMM: h_out[NN x 256] = relu(h0) @ W_lin + b_lin   (2-product fp16)
    {
        dim3 grid(HD / 128, MPAD / 128);
        k_mma<<<grid, 256, SMEM_GEMM>>>(Rh, Rl, WlT, out, HD, HD, blin, NN);
    }
}

// round 11
// speedup vs baseline: 1.8601x; 1.0524x over previous
#include <cuda_runtime.h>
#include <cuda_fp16.h>
#include <math.h>
#include <stdint.h>

// Problem constants
#define NN    30000
#define NE    480000
#define HD    256
#define MPAD  30080      // 235*128
#define KTOT  768        // x_aug | h | t1
#define NCOL  1024       // 4 gates * 256 (gate-blocked: col = g*256 + j)
#define NH    (NN * HD)

// ---------------- static device scratch ----------------
__device__ float g_deg[NN];
__device__ int   g_cnt_src[NN], g_cnt_dst[NN];
__device__ int   g_off_src[NN], g_off_dst[NN];
__device__ int   g_cur_src[NN], g_cur_dst[NN];
__device__ int   g_nbr_src[NE];                   // resolved: snid[e] bucketed by src
__device__ int   g_nbr_dst[NE];                   // resolved: dnid[e] bucketed by dst
__device__ int   g_hsrc[NE];                      // resolved: src[e]  bucketed by dst
__device__ float g_nrm[NE];                       // resolved: norm_e  bucketed by dst
__device__ float g_Z[MPAD * NCOL];                // gate pre-activations (fp32)
__device__ __align__(16) __half g_Ah[MPAD * KTOT];   // A hi (fp16); pad rows stay 0
__device__ __align__(16) __half g_Al[MPAD * KTOT];   // A lo (fp16)
__device__ __align__(16) __half g_W [NCOL * KTOT];   // W transposed [n][k], single fp16
__device__ __align__(16) __half g_Rh[MPAD * HD];     // relu(h0) hi
__device__ __align__(16) __half g_Rl[MPAD * HD];     // relu(h0) lo
__device__ __align__(16) __half g_WlT[HD * HD];      // W_lin transposed, single fp16

__device__ __forceinline__ float sigf(float x) { return 1.0f / (1.0f + __expf(-x)); }
__device__ __forceinline__ float tanhfast(float x) {
    return 2.0f / (1.0f + __expf(-2.0f * x)) - 1.0f;
}

__device__ __forceinline__ uint32_t smem_u32(const void* p) {
    uint32_t a;
    asm("{ .reg .u64 t; cvta.to.shared.u64 t, %1; cvt.u32.u64 %0, t; }" : "=r"(a) : "l"(p));
    return a;
}

// ---------------- CSR build ----------------
__global__ __launch_bounds__(256) void k_zero() {
    int i = blockIdx.x * blockDim.x + threadIdx.x;
    if (i < NN) { g_cnt_src[i] = 0; g_cnt_dst[i] = 0; g_deg[i] = 0.f; }
}

__global__ __launch_bounds__(256) void k_count(const int* __restrict__ src,
                                               const int* __restrict__ dst,
                                               const float* __restrict__ ew) {
    int e = blockIdx.x * blockDim.x + threadIdx.x;
    if (e < NE) {
        int s = src[e], d = dst[e];
        atomicAdd(&g_cnt_src[s], 1);
        atomicAdd(&g_cnt_dst[d], 1);
        atomicAdd(&g_deg[s], ew[e]);
    }
}

__global__ __launch_bounds__(256) void k_dinv() {
    int i = blockIdx.x * blockDim.x + threadIdx.x;
    if (i < NN) {
        float d = g_deg[i];
        g_deg[i] = (d > 0.f) ? rsqrtf(fmaxf(d, 1e-12f)) : 0.f;
    }
}

#define SCH 30   // 1024*30 = 30720 >= NN
__global__ __launch_bounds__(1024) void k_scan() {
    __shared__ int sh[1024];
    int t = threadIdx.x;
    int base = t * SCH;
#pragma unroll 1
    for (int pass = 0; pass < 2; pass++) {
        const int* cnt = pass ? g_cnt_dst : g_cnt_src;
        int* off = pass ? g_off_dst : g_off_src;
        int* cur = pass ? g_cur_dst : g_cur_src;
        int local = 0;
        for (int i = 0; i < SCH; i++) {
            int idx = base + i;
            if (idx < NN) local += cnt[idx];
        }
        sh[t] = local;
        __syncthreads();
        for (int o = 1; o < 1024; o <<= 1) {
            int v = 0;
            if (t >= o) v = sh[t - o];
            __syncthreads();
            if (t >= o) sh[t] += v;
            __syncthreads();
        }
        int run = (t > 0) ? sh[t - 1] : 0;
        for (int i = 0; i < SCH; i++) {
            int idx = base + i;
            if (idx < NN) {
                off[idx] = run;
                cur[idx] = run;
                run += cnt[idx];
            }
        }
        __syncthreads();
    }
}

__global__ __launch_bounds__(256) void k_fill(const int* __restrict__ src,
                                              const int* __restrict__ dst,
                                              const int* __restrict__ snid,
                                              const int* __restrict__ dnid,
                                              const float* __restrict__ ew) {
    int e = blockIdx.x * blockDim.x + threadIdx.x;
    if (e < NE) {
        int s = src[e], d = dst[e];
        int ps = atomicAdd(&g_cur_src[s], 1);
        g_nbr_src[ps] = snid[e];
        int pd = atomicAdd(&g_cur_dst[d], 1);
        g_nbr_dst[pd] = dnid[e];
        g_hsrc[pd] = s;
        g_nrm[pd] = -g_deg[s] * ew[e] * g_deg[d];
    }
}

// ---------------- fp32 -> fp16 hi/lo split ----------------
__device__ __forceinline__ void split4h(float4 v, uint2& hi, uint2& lo) {
    __half h[4], l[4];
    float f[4] = {v.x, v.y, v.z, v.w};
#pragma unroll
    for (int t = 0; t < 4; t++) {
        h[t] = __float2half(f[t]);
        l[t] = __float2half(f[t] - __half2float(h[t]));
    }
    hi = *reinterpret_cast<uint2*>(h);
    lo = *reinterpret_cast<uint2*>(l);
}

// ---------------- gather + pack A (fp16 split), no FP atomics, no eid indirection ----
__global__ __launch_bounds__(256) void k_gatherA(
    const float* __restrict__ x, const float* __restrict__ h)
{
    int node = blockIdx.x * 4 + (threadIdx.x >> 6);
    int t = threadIdx.x & 63;
    if (node >= NN) return;

    const float4* x4 = reinterpret_cast<const float4*>(x);
    const float4* h4 = reinterpret_cast<const float4*>(h);

    float4 ax = x4[(size_t)node * 64 + t];
    float4 at = make_float4(0.f, 0.f, 0.f, 0.f);

    {
        int o = g_off_src[node], c = g_cnt_src[node];
#pragma unroll 4
        for (int i = 0; i < c; i++) {
            int sn = g_nbr_src[o + i];
            float4 v = x4[(size_t)sn * 64 + t];
            ax.x += v.x; ax.y += v.y; ax.z += v.z; ax.w += v.w;
        }
    }
    {
        int o = g_off_dst[node], c = g_cnt_dst[node];
#pragma unroll 4
        for (int i = 0; i < c; i++) {
            int dn = g_nbr_dst[o + i];
            int s  = g_hsrc[o + i];
            float nm = g_nrm[o + i];
            float4 v = x4[(size_t)dn * 64 + t];
            ax.x += v.x; ax.y += v.y; ax.z += v.z; ax.w += v.w;
            float4 hv = h4[(size_t)s * 64 + t];
            at.x += nm * hv.x; at.y += nm * hv.y; at.z += nm * hv.z; at.w += nm * hv.w;
        }
    }

    float4 hr = h4[(size_t)node * 64 + t];

    uint2 hi, lo;
    size_t rb = (size_t)node * KTOT;
    split4h(ax, hi, lo);
    *reinterpret_cast<uint2*>(g_Ah + rb + t * 4) = hi;
    *reinterpret_cast<uint2*>(g_Al + rb + t * 4) = lo;
    split4h(hr, hi, lo);
    *reinterpret_cast<uint2*>(g_Ah + rb + 256 + t * 4) = hi;
    *reinterpret_cast<uint2*>(g_Al + rb + 256 + t * 4) = lo;
    split4h(at, hi, lo);
    *reinterpret_cast<uint2*>(g_Ah + rb + 512 + t * 4) = hi;
    *reinterpret_cast<uint2*>(g_Al + rb + 512 + t * 4) = lo;
}

// ---------------- weight packs (single fp16) ----------------
__global__ __launch_bounds__(256) void k_conv_W(
    const float* __restrict__ Wi, const float* __restrict__ Wf,
    const float* __restrict__ Wg, const float* __restrict__ Wo,
    const float* __restrict__ Wci, const float* __restrict__ Wcf,
    const float* __restrict__ Wcg, const float* __restrict__ Wco)
{
    int i = blockIdx.x * blockDim.x + threadIdx.x;   // over NCOL*96
    if (i >= NCOL * 96) return;
    int n = i / 96;
    int kc = i % 96;
    int g = n >> 8, j = n & 255;
    const float* Win[4] = {Wi, Wf, Wg, Wo};
    const float* Wc[4]  = {Wci, Wcf, Wcg, Wco};
    __half v[8];
#pragma unroll
    for (int t = 0; t < 8; t++) {
        int k = kc * 8 + t;
        float f;
        if (k < 256)      f = Win[g][k * 256 + j];
        else if (k < 512) f = Wc[g][(k - 256) * 256 + j];
        else              f = Wc[g][65536 + (k - 512) * 256 + j];
        v[t] = __float2half(f);
    }
    reinterpret_cast<uint4*>(g_W)[i] = *reinterpret_cast<uint4*>(v);
}

__global__ __launch_bounds__(256) void k_conv_Wlin(const float* __restrict__ Wlin) {
    int i = blockIdx.x * blockDim.x + threadIdx.x;   // over 256*32
    if (i >= HD * 32) return;
    int n = i / 32;
    int kc = i % 32;
    __half v[8];
#pragma unroll
    for (int t = 0; t < 8; t++) v[t] = __float2half(Wlin[(kc * 8 + t) * 256 + n]);
    reinterpret_cast<uint4*>(g_WlT)[i] = *reinterpret_cast<uint4*>(v);
}

// ============ fp16 2-product GEMM via mma.sync ============
// C = (Ah + Al)[M x K] @ B^T, B stored [Ncols x K] row-major fp16.
// CTA tile 128x256, 512 threads (16 warps, 2x8), warp tile 64x32,
// K-tile 32, 3-stage cp.async pipeline.
#define BKG   32
#define NSTG  3
#define TSTR  80                    // 64B payload + 16B pad; conflict-free ldmatrix
#define A_TILEB (128 * TSTR)        // 10240 B (per A operand)
#define B_TILEB (256 * TSTR)        // 20480 B
#define STAGEB  (2 * A_TILEB + B_TILEB)   // 40960 B
#define SMEM_GEMM (NSTG * STAGEB)   // 122880 B
#define NTHR  512

__device__ __forceinline__ void cp16(uint32_t saddr, const void* gaddr) {
    asm volatile("cp.async.cg.shared.global [%0], [%1], 16;" :: "r"(saddr), "l"(gaddr));
}
__device__ __forceinline__ void ldm_x4(uint32_t* r, uint32_t a) {
    asm volatile("ldmatrix.sync.aligned.m8n8.x4.shared.b16 {%0,%1,%2,%3}, [%4];"
                 : "=r"(r[0]), "=r"(r[1]), "=r"(r[2]), "=r"(r[3]) : "r"(a));
}
__device__ __forceinline__ void ldm_x2(uint32_t* r, uint32_t a) {
    asm volatile("ldmatrix.sync.aligned.m8n8.x2.shared.b16 {%0,%1}, [%2];"
                 : "=r"(r[0]), "=r"(r[1]) : "r"(a));
}
__device__ __forceinline__ void mma16816h(float* c, const uint32_t* a, const uint32_t* b) {
    asm volatile(
        "mma.sync.aligned.m16n8k16.row.col.f32.f16.f16.f32 "
        "{%0,%1,%2,%3}, {%4,%5,%6,%7}, {%8,%9}, {%0,%1,%2,%3};"
        : "+f"(c[0]), "+f"(c[1]), "+f"(c[2]), "+f"(c[3])
        : "r"(a[0]), "r"(a[1]), "r"(a[2]), "r"(a[3]), "r"(b[0]), "r"(b[1]));
}

__global__ __launch_bounds__(NTHR) void k_mma(
    const __half* __restrict__ Ah, const __half* __restrict__ Al,
    const __half* __restrict__ B,
    float* __restrict__ C, int K, int Ncols, const float* __restrict__ bias, int m_limit)
{
    extern __shared__ char smem[];
    const int tid = threadIdx.x;
    const int wid = tid >> 5;
    const int lane = tid & 31;
    const int m0 = blockIdx.y * 128;
    const int n0 = blockIdx.x * 256;
    const int nkt = K / BKG;
    const uint32_t sb = smem_u32(smem);

    const int wr = (wid >> 3) * 64;    // 2 row-groups of warps
    const int wc = (wid & 7) * 32;     // 8 col-groups

    // cp.async chunk coords: per stage, Ah/Al have 512 chunks each (128 rows x 4),
    // B has 1024 chunks (256 rows x 4). 2048 chunks / 512 threads = 4 per thread.
    const int rA = tid >> 2, cA = tid & 3;            // A rows 0..127 (k=0: Ah, k=1: Al)
    const int rB0 = tid >> 2, cB0 = tid & 3;          // B rows 0..127
    const int rB1 = (tid + 512) >> 2, cB1 = tid & 3;  // B rows 128..255

    float acc[4][4][4] = {};

    auto issue_stage = [&](int kt, int buf) {
        uint32_t s = sb + buf * STAGEB;
        const char* ahB = reinterpret_cast<const char*>(Ah);
        const char* alB = reinterpret_cast<const char*>(Al);
        const char* bB  = reinterpret_cast<const char*>(B);
        size_t kb = (size_t)kt * BKG * 2;
        {
            size_t ga = ((size_t)(m0 + rA) * K) * 2 + kb + cA * 16;
            uint32_t so = rA * TSTR + cA * 16;
            cp16(s + so, ahB + ga);
            cp16(s + A_TILEB + so, alB + ga);
        }
        {
            size_t gb = ((size_t)(n0 + rB0) * K) * 2 + kb + cB0 * 16;
            uint32_t so = rB0 * TSTR + cB0 * 16;
            cp16(s + 2 * A_TILEB + so, bB + gb);
        }
        {
            size_t gb = ((size_t)(n0 + rB1) * K) * 2 + kb + cB1 * 16;
            uint32_t so = rB1 * TSTR + cB1 * 16;
            cp16(s + 2 * A_TILEB + so, bB + gb);
        }
    };

    for (int s = 0; s < NSTG - 1; s++) {
        if (s < nkt) issue_stage(s, s);
        asm volatile("cp.async.commit_group;");
    }

    for (int kt = 0; kt < nkt; kt++) {
        asm volatile("cp.async.wait_group %0;" :: "n"(NSTG - 2));
        __syncthreads();

        uint32_t s = sb + (kt % NSTG) * STAGEB;
        uint32_t sAh = s, sAl = s + A_TILEB, sB = s + 2 * A_TILEB;

#pragma unroll
        for (int ks = 0; ks < 2; ks++) {
            uint32_t ah[4][4], al[4][4], bh[4][2];
            uint32_t aoff = (wr + (lane & 15)) * TSTR + ks * 32 + ((lane >> 4) & 1) * 16;
#pragma unroll
            for (int mt = 0; mt < 4; mt++) {
                ldm_x4(ah[mt], sAh + aoff + mt * 16 * TSTR);
                ldm_x4(al[mt], sAl + aoff + mt * 16 * TSTR);
            }
            int l = lane & 15;
            uint32_t boff = (wc + (l & 7)) * TSTR + ks * 32 + ((l >> 3) & 1) * 16;
#pragma unroll
            for (int nt = 0; nt < 4; nt++) {
                ldm_x2(bh[nt], sB + boff + nt * 8 * TSTR);
            }
#pragma unroll
            for (int mt = 0; mt < 4; mt++)
#pragma unroll
                for (int nt = 0; nt < 4; nt++) {
                    mma16816h(acc[mt][nt], ah[mt], bh[nt]);
                    mma16816h(acc[mt][nt], al[mt], bh[nt]);
                }
        }
        __syncthreads();
        int nk = kt + NSTG - 1;
        if (nk < nkt) issue_stage(nk, nk % NSTG);
        asm volatile("cp.async.commit_group;");
    }

#pragma unroll
    for (int mt = 0; mt < 4; mt++) {
        int rAo = m0 + wr + mt * 16 + (lane >> 2);
        int rBo = rAo + 8;
#pragma unroll
        for (int nt = 0; nt < 4; nt++) {
            int col = n0 + wc + nt * 8 + (lane & 3) * 2;
            float bx = 0.f, by = 0.f;
            if (bias) { bx = bias[col]; by = bias[col + 1]; }
            if (rAo < m_limit) {
                float2 v = make_float2(acc[mt][nt][0] + bx, acc[mt][nt][1] + by);
                *reinterpret_cast<float2*>(C + (size_t)rAo * Ncols + col) = v;
            }
            if (rBo < m_limit) {
                float2 v = make_float2(acc[mt][nt][2] + bx, acc[mt][nt][3] + by);
                *reinterpret_cast<float2*>(C + (size_t)rBo * Ncols + col) = v;
            }
        }
    }
}

// ---------------- gates: h0, c_new, relu split (fp16) ----------------
__global__ __launch_bounds__(256) void k_gates(
    const float* __restrict__ c,
    const float* __restrict__ bci, const float* __restrict__ bcf,
    const float* __restrict__ bcg, const float* __restrict__ bco,
    const float* __restrict__ bi, const float* __restrict__ bf,
    const float* __restrict__ bg, const float* __restrict__ bo,
    const float* __restrict__ wci, const float* __restrict__ wcf,
    const float* __restrict__ wco,
    float* __restrict__ out)
{
    int idx = blockIdx.x * blockDim.x + threadIdx.x;
    if (idx >= MPAD * HD) return;
    int row = idx >> 8;
    int j = idx & 255;
    if (row >= NN) {
        g_Rh[idx] = __float2half(0.f);
        g_Rl[idx] = __float2half(0.f);
        return;
    }
    const float* z = g_Z + (size_t)row * NCOL;
    float cv = c[idx];
    float ig = sigf(z[j]       + bci[j] + bi[j] + wci[j] * cv);
    float fg = sigf(z[256 + j] + bcf[j] + bf[j] + wcf[j] * cv);
    float gg = tanhfast(z[512 + j] + bcg[j] + bg[j]);
    float cn = fg * cv + ig * gg;
    float og = sigf(z[768 + j] + bco[j] + bo[j] + wco[j] * cn);
    float h0 = og * tanhfast(cn);
    out[NH + idx]     = h0;
    out[2 * NH + idx] = cn;
    float r = fmaxf(h0, 0.f);
    __half rh = __float2half(r);
    __half rl = __float2half(r - __half2float(rh));
    g_Rh[idx] = rh;
    g_Rl[idx] = rl;
}

// ---------------- launch ----------------
extern "C" void kernel_launch(void* const* d_in, const int* in_sizes, int n_in,
                              void* d_out, int out_size) {
    const float* x    = (const float*)d_in[0];
    const int*   ei   = (const int*)d_in[1];
    const float* ew   = (const float*)d_in[2];
    const float* h    = (const float*)d_in[3];
    const float* c    = (const float*)d_in[4];
    const int*   snid = (const int*)d_in[5];
    const int*   dnid = (const int*)d_in[6];
    const float* Wi   = (const float*)d_in[7];
    const float* Wf   = (const float*)d_in[8];
    const float* Wg   = (const float*)d_in[9];
    const float* Wo   = (const float*)d_in[10];
    const float* Wci  = (const float*)d_in[11];
    const float* Wcf  = (const float*)d_in[12];
    const float* Wcg  = (const float*)d_in[13];
    const float* Wco  = (const float*)d_in[14];
    const float* bci  = (const float*)d_in[15];
    const float* bcf  = (const float*)d_in[16];
    const float* bcg  = (const float*)d_in[17];
    const float* bco  = (const float*)d_in[18];

    const float *bi, *bf, *bg, *bo, *blin, *wci, *wcf, *wco, *Wlin;
    if (in_sizes[27] == 65536) {
        bi = (const float*)d_in[19]; bf = (const float*)d_in[20];
        bg = (const float*)d_in[21]; bo = (const float*)d_in[22];
        blin = (const float*)d_in[23];
        wci = (const float*)d_in[24]; wcf = (const float*)d_in[25];
        wco = (const float*)d_in[26];
        Wlin = (const float*)d_in[27];
    } else {
        wci = (const float*)d_in[19]; wcf = (const float*)d_in[20];
        wco = (const float*)d_in[21];
        bi = (const float*)d_in[22]; bf = (const float*)d_in[23];
        bg = (const float*)d_in[24]; bo = (const float*)d_in[25];
        Wlin = (const float*)d_in[26];
        blin = (const float*)d_in[27];
    }

    const int* src = ei;
    const int* dst = ei + NE;
    float* out = (float*)d_out;

    cudaFuncSetAttribute(k_mma, cudaFuncAttributeMaxDynamicSharedMemorySize, SMEM_GEMM);

    // CSR build (field-resolving) + weight packs
    k_zero<<<(NN + 255) / 256, 256>>>();
    k_conv_W<<<(NCOL * 96 + 255) / 256, 256>>>(Wi, Wf, Wg, Wo, Wci, Wcf, Wcg, Wco);
    k_conv_Wlin<<<(HD * 32 + 255) / 256, 256>>>(Wlin);
    k_count<<<(NE + 255) / 256, 256>>>(src, dst, ew);
    k_dinv<<<(NN + 255) / 256, 256>>>();
    k_scan<<<1, 1024>>>();
    k_fill<<<(NE + 255) / 256, 256>>>(src, dst, snid, dnid, ew);

    // gather + pack A directly
    k_gatherA<<<(NN + 3) / 4, 256>>>(x, h);

    __half *Ah, *Al, *Wp, *Rh, *Rl, *WlT;
    float *Zp;
    cudaGetSymbolAddress((void**)&Ah, g_Ah);
    cudaGetSymbolAddress((void**)&Al, g_Al);
    cudaGetSymbolAddress((void**)&Wp, g_W);
    cudaGetSymbolAddress((void**)&Zp, g_Z);
    cudaGetSymbolAddress((void**)&Rh, g_Rh);
    cudaGetSymbolAddress((void**)&Rl, g_Rl);
    cudaGetSymbolAddress((void**)&WlT, g_WlT);

    // big GEMM: Z[MPAD x 1024] = (Ah+Al) @ W^T   (2-product fp16, 128x256 CTA tile)
    {
        dim3 grid(NCOL / 256, MPAD / 128);
        k_mma<<<grid, NTHR, SMEM_GEMM>>>(Ah, Al, Wp, Zp, KTOT, NCOL, nullptr, MPAD);
    }

    k_gates<<<(MPAD * HD + 255) / 256, 256>>>(c, bci, bcf, bcg, bco, bi, bf, bg, bo,
                                              wci, wcf, wco, out);

    // small GEMM: h_out[NN x 256] = relu(h0) @ W_lin + b_lin   (2-product fp16)
    {
        dim3 grid(HD / 256, MPAD / 128);
        k_mma<<<grid, NTHR, SMEM_GEMM>>>(Rh, Rl, WlT, out, HD, HD, blin, NN);
    }
}